// round 1
// baseline (speedup 1.0000x reference)
#include <cuda_runtime.h>

#define NN 100000
#define EE 1600000
#define FF 128

// ---- scratch (device globals; no dynamic allocation allowed) ----
__device__ int   g_deg_out[NN];
__device__ int   g_deg_in[NN];
__device__ float g_ns[NN];
__device__ float g_nd[NN];
__device__ float g_y[NN * FF];     // message buffer: h * ns
__device__ float g_agg[NN * FF];   // scatter accumulator

// ------------------------------------------------------------------
__global__ void zero_deg_kernel() {
    int i = blockIdx.x * blockDim.x + threadIdx.x;
    if (i < NN) { g_deg_out[i] = 0; g_deg_in[i] = 0; }
}

__global__ void deg_kernel(const int* __restrict__ src, const int* __restrict__ dst) {
    int e = blockIdx.x * blockDim.x + threadIdx.x;
    if (e < EE) {
        atomicAdd(&g_deg_out[src[e]], 1);
        atomicAdd(&g_deg_in[dst[e]], 1);
    }
}

__global__ void norm_kernel() {
    int i = blockIdx.x * blockDim.x + threadIdx.x;
    if (i < NN) {
        int dn = g_deg_out[i];
        int dd = g_deg_in[i];
        g_ns[i] = dn > 0 ? rsqrtf((float)dn) : 0.0f;
        g_nd[i] = dd > 0 ? rsqrtf((float)dd) : 0.0f;
    }
}

__global__ void zero_agg_kernel() {
    int i = blockIdx.x * blockDim.x + threadIdx.x;   // one float4 per thread
    float4 z = make_float4(0.f, 0.f, 0.f, 0.f);
    ((float4*)g_agg)[i] = z;                          // grid sized exactly NN*FF/4
}

__device__ __forceinline__ float warp_sum(float v) {
    #pragma unroll
    for (int o = 16; o > 0; o >>= 1) v += __shfl_xor_sync(0xffffffffu, v, o);
    return v;
}

// ------------------------------------------------------------------
// Fused MLP: x=[feat|emb[label]] (256) -> relu(LN(x@W1+b1)) (512) -> @W2+b2 (128)
// -> *ns -> g_y.   16 rows per block, 256 threads.
// Thread layout: warp p (=tid>>5) owns rows {p, p+8}; lane cl owns cols cl+32*jj.
__global__ void __launch_bounds__(256) mlp_kernel(
    const float* __restrict__ feat, const int* __restrict__ labels,
    const float* __restrict__ emb,
    const float* __restrict__ W1, const float* __restrict__ b1,
    const float* __restrict__ g1, const float* __restrict__ be1,
    const float* __restrict__ W2, const float* __restrict__ b2)
{
    __shared__ float sB[16 * 512];   // 32 KB: W1 k-tile, then h1 (post-LN)
    __shared__ float sA[16 * 256];   // 16 KB: x tile, then W2 k-tile

    const int tid = threadIdx.x;
    const int n0  = blockIdx.x * 16;
    const int p   = tid >> 5;        // 0..7  (rows p and p+8)
    const int cl  = tid & 31;

    // ---- load x tile: [16][256] = features | embedded label ----
    for (int i = tid; i < 16 * 256; i += 256) {
        int r = i >> 8, c = i & 255;
        float v;
        if (c < 128) v = feat[(n0 + r) * 128 + c];
        else         v = emb[labels[n0 + r] * 128 + (c - 128)];
        sA[i] = v;
    }

    // ---- GEMM1: [16,256] @ [256,512] ----
    float acc[2][16];
    #pragma unroll
    for (int i = 0; i < 2; i++)
        #pragma unroll
        for (int j = 0; j < 16; j++) acc[i][j] = 0.f;

    const float4* W14 = (const float4*)W1;
    for (int kt = 0; kt < 256; kt += 8) {
        __syncthreads();
        // stage W1 rows [kt, kt+8) : contiguous 4096 floats
        for (int i = tid; i < 1024; i += 256)
            ((float4*)sB)[i] = W14[kt * 128 + i];
        __syncthreads();
        #pragma unroll
        for (int kk = 0; kk < 8; kk++) {
            float a0 = sA[p * 256 + kt + kk];
            float a1 = sA[(p + 8) * 256 + kt + kk];
            #pragma unroll
            for (int jj = 0; jj < 16; jj++) {
                float bv = sB[kk * 512 + cl + 32 * jj];
                acc[0][jj] = fmaf(a0, bv, acc[0][jj]);
                acc[1][jj] = fmaf(a1, bv, acc[1][jj]);
            }
        }
    }
    __syncthreads();

    // ---- + b1, LayerNorm(512), *g1+be1, relu -> sB ----
    #pragma unroll
    for (int jj = 0; jj < 16; jj++) {
        float bb = __ldg(&b1[cl + 32 * jj]);
        acc[0][jj] += bb;
        acc[1][jj] += bb;
    }
    #pragma unroll
    for (int i = 0; i < 2; i++) {
        int row = p + 8 * i;
        float s = 0.f;
        #pragma unroll
        for (int jj = 0; jj < 16; jj++) s += acc[i][jj];
        float mu = warp_sum(s) * (1.0f / 512.0f);
        float v = 0.f;
        #pragma unroll
        for (int jj = 0; jj < 16; jj++) {
            float d = acc[i][jj] - mu;
            v += d * d;
        }
        float var = warp_sum(v) * (1.0f / 512.0f);
        float rstd = rsqrtf(var + 1e-5f);
        #pragma unroll
        for (int jj = 0; jj < 16; jj++) {
            int col = cl + 32 * jj;
            float x = (acc[i][jj] - mu) * rstd * __ldg(&g1[col]) + __ldg(&be1[col]);
            sB[row * 512 + col] = fmaxf(x, 0.f);
        }
    }

    // ---- GEMM2: [16,512] @ [512,128] ----
    float acc2[2][4];
    #pragma unroll
    for (int i = 0; i < 2; i++)
        #pragma unroll
        for (int j = 0; j < 4; j++) acc2[i][j] = 0.f;

    const float4* W24 = (const float4*)W2;
    for (int kt = 0; kt < 512; kt += 16) {
        __syncthreads();
        // stage W2 rows [kt, kt+16): contiguous 2048 floats into sA region
        for (int i = tid; i < 512; i += 256)
            ((float4*)sA)[i] = W24[kt * 32 + i];
        __syncthreads();
        #pragma unroll
        for (int kk = 0; kk < 16; kk++) {
            float a0 = sB[p * 512 + kt + kk];
            float a1 = sB[(p + 8) * 512 + kt + kk];
            #pragma unroll
            for (int jj = 0; jj < 4; jj++) {
                float bv = sA[kk * 128 + cl + 32 * jj];
                acc2[0][jj] = fmaf(a0, bv, acc2[0][jj]);
                acc2[1][jj] = fmaf(a1, bv, acc2[1][jj]);
            }
        }
    }

    // ---- epilogue: +b2, *ns, store y ----
    #pragma unroll
    for (int i = 0; i < 2; i++) {
        int row = n0 + p + 8 * i;
        float nsv = g_ns[row];
        #pragma unroll
        for (int jj = 0; jj < 4; jj++) {
            int col = cl + 32 * jj;
            g_y[row * 128 + col] = (acc2[i][jj] + __ldg(&b2[col])) * nsv;
        }
    }
}

// ------------------------------------------------------------------
// Scatter: one warp per edge. Lane l moves float4 chunk l of the 128-float row.
__global__ void __launch_bounds__(256) scatter_kernel(
    const int* __restrict__ src, const int* __restrict__ dst)
{
    int gw = (blockIdx.x * 256 + threadIdx.x) >> 5;   // edge id
    int lane = threadIdx.x & 31;
    if (gw >= EE) return;
    int s = src[gw];
    int d = dst[gw];
    float4 v = ((const float4*)(g_y + s * 128))[lane];
    float* ap = g_agg + d * 128 + lane * 4;
    asm volatile("red.global.add.v4.f32 [%0], {%1,%2,%3,%4};"
                 :: "l"(ap), "f"(v.x), "f"(v.y), "f"(v.z), "f"(v.w)
                 : "memory");
}

// ------------------------------------------------------------------
// Conv transform: z = relu((agg * nd) @ Wc + bc); layer1 also *ns -> g_y,
// layer2 -> d_out.  16 rows/block, 256 threads, same thread layout as MLP.
__global__ void __launch_bounds__(256) conv_kernel(
    const float* __restrict__ Wc, const float* __restrict__ bc,
    float* __restrict__ out_ext, int to_y /*1: write g_y with ns scale*/)
{
    __shared__ float sAgg[16 * 128];  // 8 KB, pre-scaled by nd
    __shared__ float sW[32 * 128];    // 16 KB

    const int tid = threadIdx.x;
    const int n0  = blockIdx.x * 16;
    const int p   = tid >> 5;
    const int cl  = tid & 31;

    // load agg tile scaled by nd
    for (int i = tid; i < 512; i += 256) {           // 512 float4 = 16*128 floats
        int r = i >> 5, c4 = i & 31;
        float4 v = ((const float4*)(g_agg + (n0 + r) * 128))[c4];
        float ndv = g_nd[n0 + r];
        v.x *= ndv; v.y *= ndv; v.z *= ndv; v.w *= ndv;
        ((float4*)sAgg)[i] = v;
    }

    float acc[2][4];
    #pragma unroll
    for (int i = 0; i < 2; i++)
        #pragma unroll
        for (int j = 0; j < 4; j++) acc[i][j] = 0.f;

    const float4* Wc4 = (const float4*)Wc;
    for (int kt = 0; kt < 128; kt += 32) {
        __syncthreads();
        for (int i = tid; i < 1024; i += 256)        // 32*128 floats
            ((float4*)sW)[i] = Wc4[kt * 32 + i];
        __syncthreads();
        #pragma unroll
        for (int kk = 0; kk < 32; kk++) {
            float a0 = sAgg[p * 128 + kt + kk];
            float a1 = sAgg[(p + 8) * 128 + kt + kk];
            #pragma unroll
            for (int jj = 0; jj < 4; jj++) {
                float bv = sW[kk * 128 + cl + 32 * jj];
                acc[0][jj] = fmaf(a0, bv, acc[0][jj]);
                acc[1][jj] = fmaf(a1, bv, acc[1][jj]);
            }
        }
    }

    #pragma unroll
    for (int i = 0; i < 2; i++) {
        int row = n0 + p + 8 * i;
        float scale = to_y ? g_ns[row] : 1.0f;
        #pragma unroll
        for (int jj = 0; jj < 4; jj++) {
            int col = cl + 32 * jj;
            float z = fmaxf(acc[i][jj] + __ldg(&bc[col]), 0.f) * scale;
            if (to_y) g_y[row * 128 + col] = z;
            else      out_ext[row * 128 + col] = z;
        }
    }
}

// ------------------------------------------------------------------
extern "C" void kernel_launch(void* const* d_in, const int* in_sizes, int n_in,
                              void* d_out, int out_size)
{
    const float* feat   = (const float*)d_in[0];
    const int*   labels = (const int*)  d_in[1];
    const int*   esrc   = (const int*)  d_in[2];
    const int*   edst   = (const int*)  d_in[3];
    const float* emb    = (const float*)d_in[4];
    const float* W1     = (const float*)d_in[5];
    const float* b1     = (const float*)d_in[6];
    const float* g1     = (const float*)d_in[7];
    const float* be1    = (const float*)d_in[8];
    const float* W2     = (const float*)d_in[9];
    const float* b2     = (const float*)d_in[10];
    const float* Wc0    = (const float*)d_in[11];
    const float* bc0    = (const float*)d_in[12];
    const float* Wc1    = (const float*)d_in[13];
    const float* bc1    = (const float*)d_in[14];
    float* out = (float*)d_out;

    // degrees + norms
    zero_deg_kernel<<<(NN + 255) / 256, 256>>>();
    deg_kernel<<<(EE + 255) / 256, 256>>>(esrc, edst);
    norm_kernel<<<(NN + 255) / 256, 256>>>();

    // MLP preprocessing -> y = (mlp(x)) * ns
    mlp_kernel<<<NN / 16, 256>>>(feat, labels, emb, W1, b1, g1, be1, W2, b2);

    // layer 1
    zero_agg_kernel<<<NN * FF / 4 / 256, 256>>>();
    scatter_kernel<<<EE * 32 / 256, 256>>>(esrc, edst);
    conv_kernel<<<NN / 16, 256>>>(Wc0, bc0, nullptr, 1);

    // layer 2
    zero_agg_kernel<<<NN * FF / 4 / 256, 256>>>();
    scatter_kernel<<<EE * 32 / 256, 256>>>(esrc, edst);
    conv_kernel<<<NN / 16, 256>>>(Wc1, bc1, out, 0);
}

// round 3
// speedup vs baseline: 1.3073x; 1.3073x over previous
#include <cuda_runtime.h>

#define NN 100000
#define EE 1600000
#define FF 128

// ---- scratch (device globals; no dynamic allocation allowed) ----
__device__ int   g_deg_out[NN];
__device__ int   g_deg_in[NN];
__device__ float g_ns[NN];
__device__ float g_nd[NN];
__device__ float g_y[NN * FF];     // message buffer: h * ns
__device__ float g_agg[NN * FF];   // scatter accumulator

// ------------------------------------------------------------------
__global__ void zero_deg_kernel() {
    int i = blockIdx.x * blockDim.x + threadIdx.x;
    if (i < NN) { g_deg_out[i] = 0; g_deg_in[i] = 0; }
}

__global__ void deg_kernel(const int* __restrict__ src, const int* __restrict__ dst) {
    int e = blockIdx.x * blockDim.x + threadIdx.x;
    if (e < EE) {
        atomicAdd(&g_deg_out[src[e]], 1);
        atomicAdd(&g_deg_in[dst[e]], 1);
    }
}

__global__ void norm_kernel() {
    int i = blockIdx.x * blockDim.x + threadIdx.x;
    if (i < NN) {
        int dn = g_deg_out[i];
        int dd = g_deg_in[i];
        g_ns[i] = dn > 0 ? rsqrtf((float)dn) : 0.0f;
        g_nd[i] = dd > 0 ? rsqrtf((float)dd) : 0.0f;
    }
}

__global__ void zero_agg_kernel() {
    int i = blockIdx.x * blockDim.x + threadIdx.x;   // one float4 per thread
    float4 z = make_float4(0.f, 0.f, 0.f, 0.f);
    ((float4*)g_agg)[i] = z;                          // grid sized exactly NN*FF/4
}

__device__ __forceinline__ float warp_sum(float v) {
    #pragma unroll
    for (int o = 16; o > 0; o >>= 1) v += __shfl_xor_sync(0xffffffffu, v, o);
    return v;
}

// ------------------------------------------------------------------
// Fused MLP: x=[feat|emb[label]] (256) -> relu(LN(x@W1+b1)) (512) -> @W2+b2 (128)
// -> *ns -> g_y.
// 16 rows/block, 128 threads (4 warps). Warp w owns rows {w, w+4, w+8, w+12};
// lane cl owns cols cl+32*jj. 4 rows/thread amortizes B-operand shared loads.
// Static shared (48 KB exactly): sX = 16*256 (x tile, then W2 k-tiles),
//                                sH = 16*512 (W1 k-tiles, then h1 post-LN).
__global__ void __launch_bounds__(128) mlp_kernel(
    const float* __restrict__ feat, const int* __restrict__ labels,
    const float* __restrict__ emb,
    const float* __restrict__ W1, const float* __restrict__ b1,
    const float* __restrict__ g1, const float* __restrict__ be1,
    const float* __restrict__ W2, const float* __restrict__ b2)
{
    __shared__ float sX[16 * 256];   // 16 KB
    __shared__ float sH[16 * 512];   // 32 KB

    const int tid = threadIdx.x;
    const int n0  = blockIdx.x * 16;
    const int w   = tid >> 5;        // warp 0..3
    const int cl  = tid & 31;

    // ---- load x tile: [16][256] = features | embedded label (float4 path) ----
    for (int i = tid; i < 512; i += 128) {           // 512 float4 per half
        int r = i >> 5, c4 = i & 31;
        ((float4*)sX)[r * 64 + c4] = ((const float4*)feat)[(size_t)(n0 + r) * 32 + c4];
        int lab = __ldg(&labels[n0 + r]);
        ((float4*)sX)[r * 64 + 32 + c4] = ((const float4*)emb)[lab * 32 + c4];
    }

    // ---- GEMM1: [16,256] @ [256,512] ----
    float acc[4][16];
    #pragma unroll
    for (int i = 0; i < 4; i++)
        #pragma unroll
        for (int j = 0; j < 16; j++) acc[i][j] = 0.f;

    for (int kt = 0; kt < 256; kt += 16) {
        __syncthreads();                              // guards sX load / prev tile reads
        // stage W1 rows [kt, kt+16): contiguous 8192 floats
        const float4* wsrc = (const float4*)(W1 + kt * 512);
        for (int i = tid; i < 2048; i += 128) ((float4*)sH)[i] = wsrc[i];
        __syncthreads();
        #pragma unroll
        for (int kk4 = 0; kk4 < 16; kk4 += 4) {
            float a[4][4];
            #pragma unroll
            for (int i = 0; i < 4; i++) {
                float4 v = *(const float4*)&sX[(w + 4 * i) * 256 + kt + kk4];
                a[i][0] = v.x; a[i][1] = v.y; a[i][2] = v.z; a[i][3] = v.w;
            }
            #pragma unroll
            for (int kk = 0; kk < 4; kk++) {
                #pragma unroll
                for (int jj = 0; jj < 16; jj++) {
                    float bv = sH[(kk4 + kk) * 512 + cl + 32 * jj];
                    #pragma unroll
                    for (int i = 0; i < 4; i++)
                        acc[i][jj] = fmaf(a[i][kk], bv, acc[i][jj]);
                }
            }
        }
    }
    __syncthreads();   // all warps done reading sH (W1 tile) before h1 overwrite

    // ---- + b1, LayerNorm(512), *g1+be1, relu -> sH (h1) ----
    #pragma unroll
    for (int jj = 0; jj < 16; jj++) {
        float bb = __ldg(&b1[cl + 32 * jj]);
        #pragma unroll
        for (int i = 0; i < 4; i++) acc[i][jj] += bb;
    }
    #pragma unroll
    for (int i = 0; i < 4; i++) {
        int row = w + 4 * i;
        float s = 0.f;
        #pragma unroll
        for (int jj = 0; jj < 16; jj++) s += acc[i][jj];
        float mu = warp_sum(s) * (1.0f / 512.0f);
        float v = 0.f;
        #pragma unroll
        for (int jj = 0; jj < 16; jj++) {
            float d = acc[i][jj] - mu;
            v += d * d;
        }
        float rstd = rsqrtf(warp_sum(v) * (1.0f / 512.0f) + 1e-5f);
        #pragma unroll
        for (int jj = 0; jj < 16; jj++) {
            int col = cl + 32 * jj;
            float x = (acc[i][jj] - mu) * rstd * __ldg(&g1[col]) + __ldg(&be1[col]);
            sH[row * 512 + col] = fmaxf(x, 0.f);
        }
    }

    // ---- GEMM2: [16,512] @ [512,128] ----
    float acc2[4][4];
    #pragma unroll
    for (int i = 0; i < 4; i++)
        #pragma unroll
        for (int j = 0; j < 4; j++) acc2[i][j] = 0.f;

    for (int kt = 0; kt < 512; kt += 32) {
        __syncthreads();   // iter 0: guards h1 writes & last sX reads
        // stage W2 rows [kt, kt+32): contiguous 4096 floats into sX
        const float4* wsrc = (const float4*)(W2 + kt * 128);
        for (int i = tid; i < 1024; i += 128) ((float4*)sX)[i] = wsrc[i];
        __syncthreads();
        #pragma unroll
        for (int kk4 = 0; kk4 < 32; kk4 += 4) {
            float a[4][4];
            #pragma unroll
            for (int i = 0; i < 4; i++) {
                float4 v = *(const float4*)&sH[(w + 4 * i) * 512 + kt + kk4];
                a[i][0] = v.x; a[i][1] = v.y; a[i][2] = v.z; a[i][3] = v.w;
            }
            #pragma unroll
            for (int kk = 0; kk < 4; kk++) {
                #pragma unroll
                for (int jj = 0; jj < 4; jj++) {
                    float bv = sX[(kk4 + kk) * 128 + cl + 32 * jj];
                    #pragma unroll
                    for (int i = 0; i < 4; i++)
                        acc2[i][jj] = fmaf(a[i][kk], bv, acc2[i][jj]);
                }
            }
        }
    }

    // ---- epilogue: +b2, *ns, store y ----
    #pragma unroll
    for (int i = 0; i < 4; i++) {
        int row = n0 + w + 4 * i;
        float nsv = g_ns[row];
        #pragma unroll
        for (int jj = 0; jj < 4; jj++) {
            int col = cl + 32 * jj;
            g_y[row * 128 + col] = (acc2[i][jj] + __ldg(&b2[col])) * nsv;
        }
    }
}

// ------------------------------------------------------------------
// Scatter: one warp per edge. Lane l moves float4 chunk l of the 128-float row.
__global__ void __launch_bounds__(256) scatter_kernel(
    const int* __restrict__ src, const int* __restrict__ dst)
{
    int gw = (blockIdx.x * 256 + threadIdx.x) >> 5;   // edge id
    int lane = threadIdx.x & 31;
    if (gw >= EE) return;
    int s = src[gw];
    int d = dst[gw];
    float4 v = ((const float4*)(g_y + (size_t)s * 128))[lane];
    float* ap = g_agg + (size_t)d * 128 + lane * 4;
    asm volatile("red.global.add.v4.f32 [%0], {%1,%2,%3,%4};"
                 :: "l"(ap), "f"(v.x), "f"(v.y), "f"(v.z), "f"(v.w)
                 : "memory");
}

// ------------------------------------------------------------------
// Conv transform: z = relu((agg * nd) @ Wc + bc); layer1 also *ns -> g_y,
// layer2 -> d_out.
// 64 rows/block, 256 threads (8 warps). Warp w owns rows {w + 8*i, i<8};
// 8 rows/thread amortizes B-operand shared loads. 48 KB static shared.
__global__ void __launch_bounds__(256) conv_kernel(
    const float* __restrict__ Wc, const float* __restrict__ bc,
    float* __restrict__ out_ext, int to_y /*1: write g_y with ns scale*/)
{
    __shared__ float sAgg[64 * 128];  // 32 KB, pre-scaled by nd
    __shared__ float sW[32 * 128];    // 16 KB (Wc k-tile)

    const int tid = threadIdx.x;
    const int n0  = blockIdx.x * 64;
    const int w   = tid >> 5;
    const int cl  = tid & 31;

    // load agg tile scaled by nd (zero-pad OOB rows)
    for (int i = tid; i < 2048; i += 256) {           // 2048 float4 = 64*128 floats
        int r = i >> 5, c4 = i & 31;
        int row = n0 + r;
        float4 v = make_float4(0.f, 0.f, 0.f, 0.f);
        if (row < NN) {
            v = ((const float4*)g_agg)[(size_t)row * 32 + c4];
            float ndv = g_nd[row];
            v.x *= ndv; v.y *= ndv; v.z *= ndv; v.w *= ndv;
        }
        ((float4*)sAgg)[i] = v;
    }

    float acc[8][4];
    #pragma unroll
    for (int i = 0; i < 8; i++)
        #pragma unroll
        for (int j = 0; j < 4; j++) acc[i][j] = 0.f;

    for (int kt = 0; kt < 128; kt += 32) {
        __syncthreads();                              // guards sAgg load / prev tile
        const float4* wsrc = (const float4*)(Wc + kt * 128);
        for (int i = tid; i < 1024; i += 256) ((float4*)sW)[i] = wsrc[i];
        __syncthreads();
        #pragma unroll
        for (int kk4 = 0; kk4 < 32; kk4 += 4) {
            float a[8][4];
            #pragma unroll
            for (int i = 0; i < 8; i++) {
                float4 v = *(const float4*)&sAgg[(w + 8 * i) * 128 + kt + kk4];
                a[i][0] = v.x; a[i][1] = v.y; a[i][2] = v.z; a[i][3] = v.w;
            }
            #pragma unroll
            for (int kk = 0; kk < 4; kk++) {
                #pragma unroll
                for (int jj = 0; jj < 4; jj++) {
                    float bv = sW[(kk4 + kk) * 128 + cl + 32 * jj];
                    #pragma unroll
                    for (int i = 0; i < 8; i++)
                        acc[i][jj] = fmaf(a[i][kk], bv, acc[i][jj]);
                }
            }
        }
    }

    #pragma unroll
    for (int i = 0; i < 8; i++) {
        int row = n0 + w + 8 * i;
        if (row < NN) {
            float scale = to_y ? g_ns[row] : 1.0f;
            #pragma unroll
            for (int jj = 0; jj < 4; jj++) {
                int col = cl + 32 * jj;
                float z = fmaxf(acc[i][jj] + __ldg(&bc[col]), 0.f) * scale;
                if (to_y) g_y[(size_t)row * 128 + col] = z;
                else      out_ext[(size_t)row * 128 + col] = z;
            }
        }
    }
}

// ------------------------------------------------------------------
extern "C" void kernel_launch(void* const* d_in, const int* in_sizes, int n_in,
                              void* d_out, int out_size)
{
    const float* feat   = (const float*)d_in[0];
    const int*   labels = (const int*)  d_in[1];
    const int*   esrc   = (const int*)  d_in[2];
    const int*   edst   = (const int*)  d_in[3];
    const float* emb    = (const float*)d_in[4];
    const float* W1     = (const float*)d_in[5];
    const float* b1     = (const float*)d_in[6];
    const float* g1     = (const float*)d_in[7];
    const float* be1    = (const float*)d_in[8];
    const float* W2     = (const float*)d_in[9];
    const float* b2     = (const float*)d_in[10];
    const float* Wc0    = (const float*)d_in[11];
    const float* bc0    = (const float*)d_in[12];
    const float* Wc1    = (const float*)d_in[13];
    const float* bc1    = (const float*)d_in[14];
    float* out = (float*)d_out;

    // degrees + norms
    zero_deg_kernel<<<(NN + 255) / 256, 256>>>();
    deg_kernel<<<(EE + 255) / 256, 256>>>(esrc, edst);
    norm_kernel<<<(NN + 255) / 256, 256>>>();

    // MLP preprocessing -> y = (mlp(x)) * ns
    mlp_kernel<<<NN / 16, 128>>>(feat, labels, emb, W1, b1, g1, be1, W2, b2);

    // layer 1
    zero_agg_kernel<<<NN * FF / 4 / 256, 256>>>();
    scatter_kernel<<<EE * 32 / 256, 256>>>(esrc, edst);
    conv_kernel<<<(NN + 63) / 64, 256>>>(Wc0, bc0, nullptr, 1);

    // layer 2
    zero_agg_kernel<<<NN * FF / 4 / 256, 256>>>();
    scatter_kernel<<<EE * 32 / 256, 256>>>(esrc, edst);
    conv_kernel<<<(NN + 63) / 64, 256>>>(Wc1, bc1, out, 0);
}

// round 4
// speedup vs baseline: 1.4640x; 1.1198x over previous
#include <cuda_runtime.h>
#include <mma.h>

using namespace nvcuda;

#define NN 100000
#define EE 1600000
#define FF 128

// smem strides (floats) chosen for conflict-free wmma fragment loads
#define XS  260   // X tile row stride   (A frags: bank = 4m+k, distinct)
#define HS  520   // W1-tile / h1 stride (B frags: bank = 8k+n, distinct)
#define W2S 136   // W2 tile row stride  (136 % 32 == 8, same property)

// ---- scratch (device globals; no dynamic allocation allowed) ----
__device__ int   g_deg_out[NN];
__device__ int   g_deg_in[NN];
__device__ float g_ns[NN];
__device__ float g_nd[NN];
__device__ float g_y[NN * FF];     // message buffer: h * ns
__device__ float g_agg[NN * FF];   // scatter accumulator

// ------------------------------------------------------------------
__global__ void zero_deg_kernel() {
    int i = blockIdx.x * blockDim.x + threadIdx.x;
    if (i < NN) { g_deg_out[i] = 0; g_deg_in[i] = 0; }
}

__global__ void deg_kernel(const int* __restrict__ src, const int* __restrict__ dst) {
    int e = blockIdx.x * blockDim.x + threadIdx.x;
    if (e < EE) {
        atomicAdd(&g_deg_out[src[e]], 1);
        atomicAdd(&g_deg_in[dst[e]], 1);
    }
}

__global__ void norm_kernel() {
    int i = blockIdx.x * blockDim.x + threadIdx.x;
    if (i < NN) {
        int dn = g_deg_out[i];
        int dd = g_deg_in[i];
        g_ns[i] = dn > 0 ? rsqrtf((float)dn) : 0.0f;
        g_nd[i] = dd > 0 ? rsqrtf((float)dd) : 0.0f;
    }
}

__global__ void zero_agg_kernel() {
    int i = blockIdx.x * blockDim.x + threadIdx.x;   // one float4 per thread
    float4 z = make_float4(0.f, 0.f, 0.f, 0.f);
    ((float4*)g_agg)[i] = z;                          // grid sized exactly NN*FF/4
}

__device__ __forceinline__ float warp_sum(float v) {
    #pragma unroll
    for (int o = 16; o > 0; o >>= 1) v += __shfl_xor_sync(0xffffffffu, v, o);
    return v;
}

// ------------------------------------------------------------------
// Fused MLP on tf32 tensor cores:
// x=[feat|emb[label]] (256) -> relu(LN(x@W1+b1)) (512) -> @W2+b2 (128) -> *ns -> g_y
// 16 rows/block, 128 threads (4 warps).
// GEMM1: warp w owns n-cols [w*128, w*128+128): 8 wmma accum tiles, K=256 in 8-row tiles.
// GEMM2: warp w owns n-cols [w*32, w*32+32): 2 accum tiles, K=512 in 16-row tiles.
// smem (static, 41984 B):
//   floats [0,4160)     : X tile 16x(256) stride 260         } reborn as
//   floats [4160,8320)  : W1 k-tile 8x(512) stride 520       } h1 16x(512) stride 520
//   floats [8320,10496) : W2 k-tile 16x(128) stride 136, then epilogue 16x128
__global__ void __launch_bounds__(128) mlp_kernel(
    const float* __restrict__ feat, const int* __restrict__ labels,
    const float* __restrict__ emb,
    const float* __restrict__ W1, const float* __restrict__ b1,
    const float* __restrict__ g1, const float* __restrict__ be1,
    const float* __restrict__ W2, const float* __restrict__ b2)
{
    __shared__ float sm[10496];
    float* sX  = sm;            // 16 x XS
    float* sW1 = sm + 4160;     // 8 x HS
    float* sH  = sm;            // h1: 16 x HS (reuses X + W1-tile region)
    float* sW2 = sm + 8320;     // 16 x W2S (2176 floats)

    const int tid = threadIdx.x;
    const int w   = tid >> 5;
    const int cl  = tid & 31;
    const int n0g = blockIdx.x * 16;

    // ---- load X tile: [16][256] = features | embedded label ----
    for (int i = tid; i < 1024; i += 128) {
        int r = i >> 6, c4 = i & 63;
        float4 v;
        if (c4 < 32) v = ((const float4*)feat)[(size_t)(n0g + r) * 32 + c4];
        else {
            int lab = __ldg(&labels[n0g + r]);
            v = ((const float4*)emb)[lab * 32 + (c4 - 32)];
        }
        ((float4*)(sX + r * XS))[c4] = v;
    }

    // ---- GEMM1: [16,256] @ [256,512] on tf32 ----
    wmma::fragment<wmma::accumulator, 16, 16, 8, float> c1[8];
    #pragma unroll
    for (int j = 0; j < 8; j++) wmma::fill_fragment(c1[j], 0.0f);

    const int n0 = w * 128;
    for (int kt = 0; kt < 256; kt += 8) {
        __syncthreads();
        const float4* wsrc = (const float4*)(W1 + kt * 512);
        for (int i = tid; i < 1024; i += 128) {
            int r = i >> 7, c4 = i & 127;
            ((float4*)(sW1 + r * HS))[c4] = wsrc[i];
        }
        __syncthreads();

        wmma::fragment<wmma::matrix_a, 16, 16, 8, wmma::precision::tf32, wmma::row_major> a;
        wmma::load_matrix_sync(a, sX + kt, XS);
        #pragma unroll
        for (int t = 0; t < a.num_elements; t++) a.x[t] = wmma::__float_to_tf32(a.x[t]);

        #pragma unroll
        for (int j = 0; j < 8; j++) {
            wmma::fragment<wmma::matrix_b, 16, 16, 8, wmma::precision::tf32, wmma::row_major> b;
            wmma::load_matrix_sync(b, sW1 + n0 + j * 16, HS);
            #pragma unroll
            for (int t = 0; t < b.num_elements; t++) b.x[t] = wmma::__float_to_tf32(b.x[t]);
            wmma::mma_sync(c1[j], a, b, c1[j]);
        }
    }
    __syncthreads();   // X + W1-tile dead; region becomes h1

    #pragma unroll
    for (int j = 0; j < 8; j++)
        wmma::store_matrix_sync(sH + n0 + j * 16, c1[j], HS, wmma::mem_row_major);
    __syncthreads();

    // ---- + b1, LayerNorm(512), *g1+be1, relu (in-place in sH) ----
    #pragma unroll
    for (int i = 0; i < 4; i++) {
        int r = w * 4 + i;
        float vals[16];
        float s = 0.f;
        #pragma unroll
        for (int jj = 0; jj < 16; jj++) {
            int col = cl + 32 * jj;
            vals[jj] = sH[r * HS + col] + __ldg(&b1[col]);
            s += vals[jj];
        }
        float mu = warp_sum(s) * (1.0f / 512.0f);
        float v = 0.f;
        #pragma unroll
        for (int jj = 0; jj < 16; jj++) {
            float d = vals[jj] - mu;
            v += d * d;
        }
        float rstd = rsqrtf(warp_sum(v) * (1.0f / 512.0f) + 1e-5f);
        #pragma unroll
        for (int jj = 0; jj < 16; jj++) {
            int col = cl + 32 * jj;
            float x = (vals[jj] - mu) * rstd * __ldg(&g1[col]) + __ldg(&be1[col]);
            sH[r * HS + col] = fmaxf(x, 0.f);
        }
    }
    __syncthreads();

    // ---- GEMM2: [16,512] @ [512,128] on tf32 ----
    wmma::fragment<wmma::accumulator, 16, 16, 8, float> c2[2];
    #pragma unroll
    for (int j = 0; j < 2; j++) wmma::fill_fragment(c2[j], 0.0f);

    const int n02 = w * 32;
    for (int kt = 0; kt < 512; kt += 16) {
        __syncthreads();
        const float4* wsrc = (const float4*)(W2 + kt * 128);
        for (int i = tid; i < 512; i += 128) {
            int r = i >> 5, c4 = i & 31;
            ((float4*)(sW2 + r * W2S))[c4] = wsrc[i];
        }
        __syncthreads();

        #pragma unroll
        for (int ks = 0; ks < 2; ks++) {
            wmma::fragment<wmma::matrix_a, 16, 16, 8, wmma::precision::tf32, wmma::row_major> a2;
            wmma::load_matrix_sync(a2, sH + kt + ks * 8, HS);
            #pragma unroll
            for (int t = 0; t < a2.num_elements; t++) a2.x[t] = wmma::__float_to_tf32(a2.x[t]);
            #pragma unroll
            for (int j = 0; j < 2; j++) {
                wmma::fragment<wmma::matrix_b, 16, 16, 8, wmma::precision::tf32, wmma::row_major> b;
                wmma::load_matrix_sync(b, sW2 + (ks * 8) * W2S + n02 + j * 16, W2S);
                #pragma unroll
                for (int t = 0; t < b.num_elements; t++) b.x[t] = wmma::__float_to_tf32(b.x[t]);
                wmma::mma_sync(c2[j], a2, b, c2[j]);
            }
        }
    }
    __syncthreads();

    // ---- epilogue: stage C2 to smem, +b2, *ns, store y ----
    float* sE = sW2;   // 16x128
    #pragma unroll
    for (int j = 0; j < 2; j++)
        wmma::store_matrix_sync(sE + n02 + j * 16, c2[j], 128, wmma::mem_row_major);
    __syncthreads();

    for (int i = tid; i < 2048; i += 128) {
        int r = i >> 7, col = i & 127;
        int row = n0g + r;
        g_y[(size_t)row * 128 + col] = (sE[r * 128 + col] + __ldg(&b2[col])) * g_ns[row];
    }
}

// ------------------------------------------------------------------
// Scatter: one warp per edge. Lane l moves float4 chunk l of the 128-float row.
__global__ void __launch_bounds__(256) scatter_kernel(
    const int* __restrict__ src, const int* __restrict__ dst)
{
    int gw = (blockIdx.x * 256 + threadIdx.x) >> 5;   // edge id
    int lane = threadIdx.x & 31;
    if (gw >= EE) return;
    int s = src[gw];
    int d = dst[gw];
    float4 v = ((const float4*)(g_y + (size_t)s * 128))[lane];
    float* ap = g_agg + (size_t)d * 128 + lane * 4;
    asm volatile("red.global.add.v4.f32 [%0], {%1,%2,%3,%4};"
                 :: "l"(ap), "f"(v.x), "f"(v.y), "f"(v.z), "f"(v.w)
                 : "memory");
}

// ------------------------------------------------------------------
// Conv transform: z = relu((agg * nd) @ Wc + bc); layer1 also *ns -> g_y,
// layer2 -> d_out.
// 64 rows/block, 256 threads (8 warps). 8 rows/thread. 48 KB static shared.
__global__ void __launch_bounds__(256) conv_kernel(
    const float* __restrict__ Wc, const float* __restrict__ bc,
    float* __restrict__ out_ext, int to_y /*1: write g_y with ns scale*/)
{
    __shared__ float sAgg[64 * 128];  // 32 KB, pre-scaled by nd
    __shared__ float sW[32 * 128];    // 16 KB (Wc k-tile)

    const int tid = threadIdx.x;
    const int n0  = blockIdx.x * 64;
    const int w   = tid >> 5;
    const int cl  = tid & 31;

    // load agg tile scaled by nd (zero-pad OOB rows)
    for (int i = tid; i < 2048; i += 256) {
        int r = i >> 5, c4 = i & 31;
        int row = n0 + r;
        float4 v = make_float4(0.f, 0.f, 0.f, 0.f);
        if (row < NN) {
            v = ((const float4*)g_agg)[(size_t)row * 32 + c4];
            float ndv = g_nd[row];
            v.x *= ndv; v.y *= ndv; v.z *= ndv; v.w *= ndv;
        }
        ((float4*)sAgg)[i] = v;
    }

    float acc[8][4];
    #pragma unroll
    for (int i = 0; i < 8; i++)
        #pragma unroll
        for (int j = 0; j < 4; j++) acc[i][j] = 0.f;

    for (int kt = 0; kt < 128; kt += 32) {
        __syncthreads();
        const float4* wsrc = (const float4*)(Wc + kt * 128);
        for (int i = tid; i < 1024; i += 256) ((float4*)sW)[i] = wsrc[i];
        __syncthreads();
        #pragma unroll
        for (int kk4 = 0; kk4 < 32; kk4 += 4) {
            float a[8][4];
            #pragma unroll
            for (int i = 0; i < 8; i++) {
                float4 v = *(const float4*)&sAgg[(w + 8 * i) * 128 + kt + kk4];
                a[i][0] = v.x; a[i][1] = v.y; a[i][2] = v.z; a[i][3] = v.w;
            }
            #pragma unroll
            for (int kk = 0; kk < 4; kk++) {
                #pragma unroll
                for (int jj = 0; jj < 4; jj++) {
                    float bv = sW[(kk4 + kk) * 128 + cl + 32 * jj];
                    #pragma unroll
                    for (int i = 0; i < 8; i++)
                        acc[i][jj] = fmaf(a[i][kk], bv, acc[i][jj]);
                }
            }
        }
    }

    #pragma unroll
    for (int i = 0; i < 8; i++) {
        int row = n0 + w + 8 * i;
        if (row < NN) {
            float scale = to_y ? g_ns[row] : 1.0f;
            #pragma unroll
            for (int jj = 0; jj < 4; jj++) {
                int col = cl + 32 * jj;
                float z = fmaxf(acc[i][jj] + __ldg(&bc[col]), 0.f) * scale;
                if (to_y) g_y[(size_t)row * 128 + col] = z;
                else      out_ext[(size_t)row * 128 + col] = z;
            }
        }
    }
}

// ------------------------------------------------------------------
extern "C" void kernel_launch(void* const* d_in, const int* in_sizes, int n_in,
                              void* d_out, int out_size)
{
    const float* feat   = (const float*)d_in[0];
    const int*   labels = (const int*)  d_in[1];
    const int*   esrc   = (const int*)  d_in[2];
    const int*   edst   = (const int*)  d_in[3];
    const float* emb    = (const float*)d_in[4];
    const float* W1     = (const float*)d_in[5];
    const float* b1     = (const float*)d_in[6];
    const float* g1     = (const float*)d_in[7];
    const float* be1    = (const float*)d_in[8];
    const float* W2     = (const float*)d_in[9];
    const float* b2     = (const float*)d_in[10];
    const float* Wc0    = (const float*)d_in[11];
    const float* bc0    = (const float*)d_in[12];
    const float* Wc1    = (const float*)d_in[13];
    const float* bc1    = (const float*)d_in[14];
    float* out = (float*)d_out;

    // degrees + norms
    zero_deg_kernel<<<(NN + 255) / 256, 256>>>();
    deg_kernel<<<(EE + 255) / 256, 256>>>(esrc, edst);
    norm_kernel<<<(NN + 255) / 256, 256>>>();

    // MLP preprocessing -> y = (mlp(x)) * ns
    mlp_kernel<<<NN / 16, 128>>>(feat, labels, emb, W1, b1, g1, be1, W2, b2);

    // layer 1
    zero_agg_kernel<<<NN * FF / 4 / 256, 256>>>();
    scatter_kernel<<<EE * 32 / 256, 256>>>(esrc, edst);
    conv_kernel<<<(NN + 63) / 64, 256>>>(Wc0, bc0, nullptr, 1);

    // layer 2
    zero_agg_kernel<<<NN * FF / 4 / 256, 256>>>();
    scatter_kernel<<<EE * 32 / 256, 256>>>(esrc, edst);
    conv_kernel<<<(NN + 63) / 64, 256>>>(Wc1, bc1, out, 0);
}

// round 8
// speedup vs baseline: 1.9859x; 1.3565x over previous
#include <cuda_runtime.h>
#include <mma.h>

using namespace nvcuda;

#define NN 100000
#define EE 1600000
#define FF 128

// smem strides (floats): %32 == 8 residues give conflict-free wmma frag loads
#define AS 136    // feat tile / W2 k-tile stride
#define HS 520    // W1 k-tile / h1 stride

// ---- scratch (device globals; ~105 MB, same level as passing R4) ----
__device__ int   g_deg_out[NN];
__device__ int   g_deg_in[NN];
__device__ float g_ns[NN];
__device__ float g_nd[NN];
__device__ float g_y[NN * FF];       // message buffer: h * ns
__device__ float g_agg[NN * FF];     // scatter accumulator
__device__ float g_w1r[128 * 512];   // tf32-rounded W1 top half (feat rows)
__device__ float g_w2r[512 * 128];   // tf32-rounded W2
__device__ float g_E[24 * 512];      // emb @ W1_bot + b1 (full fp32)

__device__ __forceinline__ float tf32r(float v) {
    unsigned int r;
    asm("cvt.rna.tf32.f32 %0, %1;" : "=r"(r) : "f"(v));
    return __uint_as_float(r);
}

// ------------------------------------------------------------------
__global__ void zero_deg_kernel() {
    int i = blockIdx.x * blockDim.x + threadIdx.x;
    if (i < NN) { g_deg_out[i] = 0; g_deg_in[i] = 0; }
}

__global__ void deg_kernel(const int* __restrict__ src, const int* __restrict__ dst) {
    int e = blockIdx.x * blockDim.x + threadIdx.x;
    if (e < EE) {
        atomicAdd(&g_deg_out[src[e]], 1);
        atomicAdd(&g_deg_in[dst[e]], 1);
    }
}

__global__ void norm_kernel() {
    int i = blockIdx.x * blockDim.x + threadIdx.x;
    if (i < NN) {
        int dn = g_deg_out[i];
        int dd = g_deg_in[i];
        g_ns[i] = dn > 0 ? rsqrtf((float)dn) : 0.0f;
        g_nd[i] = dd > 0 ? rsqrtf((float)dd) : 0.0f;
    }
}

__global__ void zero_agg_kernel() {
    int i = blockIdx.x * blockDim.x + threadIdx.x;
    ((float4*)g_agg)[i] = make_float4(0.f, 0.f, 0.f, 0.f);   // grid = NN*FF/4 exactly
}

__device__ __forceinline__ float warp_sum(float v) {
    #pragma unroll
    for (int o = 16; o > 0; o >>= 1) v += __shfl_xor_sync(0xffffffffu, v, o);
    return v;
}

// ------------------------------------------------------------------
// Round W1 top half + W2 to tf32 once.
__global__ void round_w_kernel(const float* __restrict__ W1, const float* __restrict__ W2)
{
    int i = blockIdx.x * blockDim.x + threadIdx.x;   // i < 131072
    if (i < 65536) g_w1r[i] = tf32r(W1[i]);
    else           g_w2r[i - 65536] = tf32r(W2[i - 65536]);
}

// E = emb @ W1_bot + b1  (fp32 exact). 24*512 outputs, K=128 each.
__global__ void prep_E_kernel(const float* __restrict__ emb, const float* __restrict__ W1,
                              const float* __restrict__ b1)
{
    int t = blockIdx.x * blockDim.x + threadIdx.x;   // t < 24*512
    int c = t >> 9, j = t & 511;
    float s = __ldg(&b1[j]);
    #pragma unroll 8
    for (int k = 0; k < 128; k++)
        s += emb[c * 128 + k] * W1[(128 + k) * 512 + j];
    g_E[t] = s;
}

// ------------------------------------------------------------------
// Fused MLP (R4-proven shape, optimized internals):
//   h_raw = feat @ W1_top            (tf32 wmma, K=128, W1 double-buffered)
//   h1    = tf32(relu(LN(h_raw + E[label]) * g1 + be1))
//   y     = (h1 @ W2 + b2) * ns      (tf32 wmma, K=512)
// 16 rows/block, 128 threads (4 warps).
// smem (static 41984 B):
//   sA: 16 x AS  (tf32 feat tile; then W2 k-tiles; then epilogue 16x128)
//   sH: 16 x HS  (W1 double-buffer 2 x 8 x HS; then h1)
__global__ void __launch_bounds__(128) mlp_kernel(
    const float* __restrict__ feat, const int* __restrict__ labels,
    const float* __restrict__ g1, const float* __restrict__ be1,
    const float* __restrict__ b2)
{
    __shared__ float sA[16 * AS];    // 8704 B
    __shared__ float sH[16 * HS];    // 33280 B

    const int tid = threadIdx.x;
    const int w   = tid >> 5;
    const int cl  = tid & 31;
    const int n0g = blockIdx.x * 16;

    // ---- load feat tile [16][128], rounded to tf32 ----
    for (int q = 0; q < 4; q++) {
        int i = tid + q * 128;            // 512 float4
        int r = i >> 5, c4 = i & 31;
        float4 v = ((const float4*)feat)[(size_t)(n0g + r) * 32 + c4];
        v.x = tf32r(v.x); v.y = tf32r(v.y); v.z = tf32r(v.z); v.w = tf32r(v.w);
        ((float4*)(sA + r * AS))[c4] = v;
    }
    // ---- stage W1 k-tile 0 (rows 0..7) into sH buffer 0 ----
    {
        const float4* src = (const float4*)g_w1r;
        #pragma unroll
        for (int q = 0; q < 8; q++) {
            int i = tid + q * 128;        // 1024 float4 = 8x512
            int r = i >> 7, c4 = i & 127;
            ((float4*)(sH + r * HS))[c4] = src[i];
        }
    }
    __syncthreads();

    // ---- GEMM1: [16,128] @ [128,512], warp w owns cols [w*128, w*128+128) ----
    wmma::fragment<wmma::accumulator, 16, 16, 8, float> c1[8];
    #pragma unroll
    for (int j = 0; j < 8; j++) wmma::fill_fragment(c1[j], 0.0f);

    const int n0 = w * 128;
    for (int kt = 0; kt < 16; kt++) {
        const float* cur = sH + (kt & 1) * (8 * HS);

        wmma::fragment<wmma::matrix_a, 16, 16, 8, wmma::precision::tf32, wmma::row_major> a;
        wmma::load_matrix_sync(a, sA + kt * 8, AS);

        #pragma unroll
        for (int j = 0; j < 8; j++) {
            wmma::fragment<wmma::matrix_b, 16, 16, 8, wmma::precision::tf32, wmma::row_major> b;
            wmma::load_matrix_sync(b, cur + n0 + j * 16, HS);
            wmma::mma_sync(c1[j], a, b, c1[j]);
        }

        if (kt < 15) {   // stage next tile into the other buffer (last read at kt-1)
            float* nxt = sH + ((kt + 1) & 1) * (8 * HS);
            const float4* src = (const float4*)g_w1r + (kt + 1) * 1024;
            #pragma unroll
            for (int q = 0; q < 8; q++) {
                int i = tid + q * 128;
                int r = i >> 7, c4 = i & 127;
                ((float4*)(nxt + r * HS))[c4] = src[i];
            }
        }
        __syncthreads();
    }

    // ---- h_raw -> sH as h1 region (stride HS) ----
    #pragma unroll
    for (int j = 0; j < 8; j++)
        wmma::store_matrix_sync(sH + n0 + j * 16, c1[j], HS, wmma::mem_row_major);
    __syncthreads();

    // ---- + E[label], LayerNorm(512), *g1+be1, relu, tf32 round (in place) ----
    #pragma unroll
    for (int i = 0; i < 4; i++) {
        int r = w * 4 + i;
        const float* Ep = g_E + __ldg(&labels[n0g + r]) * 512;
        float vals[16];
        float s = 0.f;
        #pragma unroll
        for (int jj = 0; jj < 16; jj++) {
            int col = cl + 32 * jj;
            vals[jj] = sH[r * HS + col] + __ldg(&Ep[col]);
            s += vals[jj];
        }
        float mu = warp_sum(s) * (1.0f / 512.0f);
        float v = 0.f;
        #pragma unroll
        for (int jj = 0; jj < 16; jj++) {
            float d = vals[jj] - mu;
            v += d * d;
        }
        float rstd = rsqrtf(warp_sum(v) * (1.0f / 512.0f) + 1e-5f);
        #pragma unroll
        for (int jj = 0; jj < 16; jj++) {
            int col = cl + 32 * jj;
            float x = (vals[jj] - mu) * rstd * __ldg(&g1[col]) + __ldg(&be1[col]);
            sH[r * HS + col] = tf32r(fmaxf(x, 0.f));
        }
    }

    // ---- GEMM2: [16,512] @ [512,128], warp w owns cols [w*32, w*32+32) ----
    wmma::fragment<wmma::accumulator, 16, 16, 8, float> c2[2];
    wmma::fill_fragment(c2[0], 0.0f);
    wmma::fill_fragment(c2[1], 0.0f);

    const int n02 = w * 32;
    for (int kt = 0; kt < 32; kt++) {
        __syncthreads();   // prev compute (or GEMM1 A / LN) done before sA overwrite
        const float4* src = (const float4*)g_w2r + kt * 512;
        #pragma unroll
        for (int q = 0; q < 4; q++) {
            int i = tid + q * 128;        // 512 float4 = 16x128
            int r = i >> 5, c4 = i & 31;
            ((float4*)(sA + r * AS))[c4] = src[i];
        }
        __syncthreads();

        #pragma unroll
        for (int ks = 0; ks < 2; ks++) {
            wmma::fragment<wmma::matrix_a, 16, 16, 8, wmma::precision::tf32, wmma::row_major> a2;
            wmma::load_matrix_sync(a2, sH + kt * 16 + ks * 8, HS);
            #pragma unroll
            for (int j = 0; j < 2; j++) {
                wmma::fragment<wmma::matrix_b, 16, 16, 8, wmma::precision::tf32, wmma::row_major> b;
                wmma::load_matrix_sync(b, sA + (ks * 8) * AS + n02 + j * 16, AS);
                wmma::mma_sync(c2[j], a2, b, c2[j]);
            }
        }
    }
    __syncthreads();

    // ---- epilogue: stage C2 to sA (16x128), +b2, *ns, store y ----
    #pragma unroll
    for (int j = 0; j < 2; j++)
        wmma::store_matrix_sync(sA + n02 + j * 16, c2[j], 128, wmma::mem_row_major);
    __syncthreads();

    for (int i = tid; i < 2048; i += 128) {
        int r = i >> 7, col = i & 127;
        int row = n0g + r;
        g_y[(size_t)row * 128 + col] = (sA[i] + __ldg(&b2[col])) * g_ns[row];
    }
}

// ------------------------------------------------------------------
// Scatter: one warp per edge. Lane l moves float4 chunk l of the 128-float row.
__global__ void __launch_bounds__(256) scatter_kernel(
    const int* __restrict__ src, const int* __restrict__ dst)
{
    int gw = (blockIdx.x * 256 + threadIdx.x) >> 5;
    int lane = threadIdx.x & 31;
    if (gw >= EE) return;
    int s = src[gw];
    int d = dst[gw];
    float4 v = ((const float4*)(g_y + (size_t)s * 128))[lane];
    float* ap = g_agg + (size_t)d * 128 + lane * 4;
    asm volatile("red.global.add.v4.f32 [%0], {%1,%2,%3,%4};"
                 :: "l"(ap), "f"(v.x), "f"(v.y), "f"(v.z), "f"(v.w)
                 : "memory");
}

// ------------------------------------------------------------------
// Conv transform: z = relu((agg * nd) @ Wc + bc); layer1 also *ns -> g_y,
// layer2 -> d_out.  64 rows/block, 256 threads, 8 rows/thread, 48 KB static.
__global__ void __launch_bounds__(256) conv_kernel(
    const float* __restrict__ Wc, const float* __restrict__ bc,
    float* __restrict__ out_ext, int to_y)
{
    __shared__ float sAgg[64 * 128];
    __shared__ float sW[32 * 128];

    const int tid = threadIdx.x;
    const int n0  = blockIdx.x * 64;
    const int w   = tid >> 5;
    const int cl  = tid & 31;

    for (int i = tid; i < 2048; i += 256) {
        int r = i >> 5, c4 = i & 31;
        int row = n0 + r;
        float4 v = make_float4(0.f, 0.f, 0.f, 0.f);
        if (row < NN) {
            v = ((const float4*)g_agg)[(size_t)row * 32 + c4];
            float ndv = g_nd[row];
            v.x *= ndv; v.y *= ndv; v.z *= ndv; v.w *= ndv;
        }
        ((float4*)sAgg)[i] = v;
    }

    float acc[8][4];
    #pragma unroll
    for (int i = 0; i < 8; i++)
        #pragma unroll
        for (int j = 0; j < 4; j++) acc[i][j] = 0.f;

    for (int kt = 0; kt < 128; kt += 32) {
        __syncthreads();
        const float4* wsrc = (const float4*)(Wc + kt * 128);
        for (int i = tid; i < 1024; i += 256) ((float4*)sW)[i] = wsrc[i];
        __syncthreads();
        #pragma unroll
        for (int kk4 = 0; kk4 < 32; kk4 += 4) {
            float a[8][4];
            #pragma unroll
            for (int i = 0; i < 8; i++) {
                float4 v = *(const float4*)&sAgg[(w + 8 * i) * 128 + kt + kk4];
                a[i][0] = v.x; a[i][1] = v.y; a[i][2] = v.z; a[i][3] = v.w;
            }
            #pragma unroll
            for (int kk = 0; kk < 4; kk++) {
                #pragma unroll
                for (int jj = 0; jj < 4; jj++) {
                    float bv = sW[(kk4 + kk) * 128 + cl + 32 * jj];
                    #pragma unroll
                    for (int i = 0; i < 8; i++)
                        acc[i][jj] = fmaf(a[i][kk], bv, acc[i][jj]);
                }
            }
        }
    }

    #pragma unroll
    for (int i = 0; i < 8; i++) {
        int row = n0 + w + 8 * i;
        if (row < NN) {
            float scale = to_y ? g_ns[row] : 1.0f;
            #pragma unroll
            for (int jj = 0; jj < 4; jj++) {
                int col = cl + 32 * jj;
                float z = fmaxf(acc[i][jj] + __ldg(&bc[col]), 0.f) * scale;
                if (to_y) g_y[(size_t)row * 128 + col] = z;
                else      out_ext[(size_t)row * 128 + col] = z;
            }
        }
    }
}

// ------------------------------------------------------------------
extern "C" void kernel_launch(void* const* d_in, const int* in_sizes, int n_in,
                              void* d_out, int out_size)
{
    const float* feat   = (const float*)d_in[0];
    const int*   labels = (const int*)  d_in[1];
    const int*   esrc   = (const int*)  d_in[2];
    const int*   edst   = (const int*)  d_in[3];
    const float* emb    = (const float*)d_in[4];
    const float* W1     = (const float*)d_in[5];
    const float* b1     = (const float*)d_in[6];
    const float* g1     = (const float*)d_in[7];
    const float* be1    = (const float*)d_in[8];
    const float* W2     = (const float*)d_in[9];
    const float* b2     = (const float*)d_in[10];
    const float* Wc0    = (const float*)d_in[11];
    const float* bc0    = (const float*)d_in[12];
    const float* Wc1    = (const float*)d_in[13];
    const float* bc1    = (const float*)d_in[14];
    float* out = (float*)d_out;

    // degrees + norms
    zero_deg_kernel<<<(NN + 255) / 256, 256>>>();
    deg_kernel<<<(EE + 255) / 256, 256>>>(esrc, edst);
    norm_kernel<<<(NN + 255) / 256, 256>>>();

    // one-time weight prep
    round_w_kernel<<<131072 / 256, 256>>>(W1, W2);
    prep_E_kernel<<<48, 256>>>(emb, W1, b1);

    // fused MLP -> y = mlp(x) * ns
    mlp_kernel<<<NN / 16, 128>>>(feat, labels, g1, be1, b2);

    // layer 1
    zero_agg_kernel<<<NN * FF / 4 / 256, 256>>>();
    scatter_kernel<<<EE * 32 / 256, 256>>>(esrc, edst);
    conv_kernel<<<(NN + 63) / 64, 256>>>(Wc0, bc0, nullptr, 1);

    // layer 2
    zero_agg_kernel<<<NN * FF / 4 / 256, 256>>>();
    scatter_kernel<<<EE * 32 / 256, 256>>>(esrc, edst);
    conv_kernel<<<(NN + 63) / 64, 256>>>(Wc1, bc1, out, 0);
}

// round 10
// speedup vs baseline: 2.0646x; 1.0397x over previous
// R10 = R9 resubmission (container-level failure, no harness evidence produced;
// re-running the identical experiment per theory-first discipline).
#include <cuda_runtime.h>
#include <mma.h>

using namespace nvcuda;

#define NN 100000
#define EE 1600000
#define FF 128

// smem strides (floats): %32 == 8 residues give conflict-free wmma frag loads
#define AS 136    // feat tile / W2 k-tile / conv tile stride
#define HS 520    // W1 k-tile / h1 stride

// ---- scratch (device globals; ~105 MB) ----
__device__ int   g_deg_out[NN];
__device__ int   g_deg_in[NN];
__device__ float g_ns[NN];
__device__ float g_nd[NN];
__device__ float g_y[NN * FF];       // message buffer: h * ns
__device__ float g_agg[NN * FF];     // scatter accumulator
__device__ float g_w1r[128 * 512];   // tf32-rounded W1 top half (feat rows)
__device__ float g_w2r[512 * 128];   // tf32-rounded W2
__device__ float g_wc0r[128 * 128];  // tf32-rounded Wc0
__device__ float g_wc1r[128 * 128];  // tf32-rounded Wc1
__device__ float g_E[24 * 512];      // emb @ W1_bot + b1 (full fp32)

__device__ __forceinline__ float tf32r(float v) {
    unsigned int r;
    asm("cvt.rna.tf32.f32 %0, %1;" : "=r"(r) : "f"(v));
    return __uint_as_float(r);
}

// ------------------------------------------------------------------
__global__ void zero_deg_kernel() {
    int i = blockIdx.x * blockDim.x + threadIdx.x;
    if (i < NN) { g_deg_out[i] = 0; g_deg_in[i] = 0; }
}

__global__ void deg_kernel(const int* __restrict__ src, const int* __restrict__ dst) {
    int e = blockIdx.x * blockDim.x + threadIdx.x;
    if (e < EE) {
        atomicAdd(&g_deg_out[src[e]], 1);
        atomicAdd(&g_deg_in[dst[e]], 1);
    }
}

__global__ void norm_kernel() {
    int i = blockIdx.x * blockDim.x + threadIdx.x;
    if (i < NN) {
        int dn = g_deg_out[i];
        int dd = g_deg_in[i];
        g_ns[i] = dn > 0 ? rsqrtf((float)dn) : 0.0f;
        g_nd[i] = dd > 0 ? rsqrtf((float)dd) : 0.0f;
    }
}

__global__ void zero_agg_kernel() {
    int i = blockIdx.x * blockDim.x + threadIdx.x;
    ((float4*)g_agg)[i] = make_float4(0.f, 0.f, 0.f, 0.f);   // grid = NN*FF/4 exactly
}

__device__ __forceinline__ float warp_sum(float v) {
    #pragma unroll
    for (int o = 16; o > 0; o >>= 1) v += __shfl_xor_sync(0xffffffffu, v, o);
    return v;
}

// ------------------------------------------------------------------
// Round W1 top half + W2 + Wc0 + Wc1 to tf32 once. 163840 elements.
__global__ void round_w_kernel(const float* __restrict__ W1, const float* __restrict__ W2,
                               const float* __restrict__ Wc0, const float* __restrict__ Wc1)
{
    int i = blockIdx.x * blockDim.x + threadIdx.x;
    if (i < 65536)       g_w1r[i] = tf32r(W1[i]);
    else if (i < 131072) g_w2r[i - 65536] = tf32r(W2[i - 65536]);
    else if (i < 147456) g_wc0r[i - 131072] = tf32r(Wc0[i - 131072]);
    else                 g_wc1r[i - 147456] = tf32r(Wc1[i - 147456]);
}

// E = emb @ W1_bot + b1  (fp32 exact). 24*512 outputs, K=128 each.
__global__ void prep_E_kernel(const float* __restrict__ emb, const float* __restrict__ W1,
                              const float* __restrict__ b1)
{
    int t = blockIdx.x * blockDim.x + threadIdx.x;   // t < 24*512
    int c = t >> 9, j = t & 511;
    float s = __ldg(&b1[j]);
    #pragma unroll 8
    for (int k = 0; k < 128; k++)
        s += emb[c * 128 + k] * W1[(128 + k) * 512 + j];
    g_E[t] = s;
}

// ------------------------------------------------------------------
// Fused MLP (proven R8 shape):
//   h_raw = feat @ W1_top            (tf32 wmma, K=128, W1 double-buffered)
//   h1    = tf32(relu(LN(h_raw + E[label]) * g1 + be1))
//   y     = (h1 @ W2 + b2) * ns      (tf32 wmma, K=512)
// 16 rows/block, 128 threads (4 warps). Static smem 41984 B.
__global__ void __launch_bounds__(128) mlp_kernel(
    const float* __restrict__ feat, const int* __restrict__ labels,
    const float* __restrict__ g1, const float* __restrict__ be1,
    const float* __restrict__ b2)
{
    __shared__ float sA[16 * AS];    // 8704 B
    __shared__ float sH[16 * HS];    // 33280 B

    const int tid = threadIdx.x;
    const int w   = tid >> 5;
    const int cl  = tid & 31;
    const int n0g = blockIdx.x * 16;

    // ---- load feat tile [16][128], rounded to tf32 ----
    for (int q = 0; q < 4; q++) {
        int i = tid + q * 128;            // 512 float4
        int r = i >> 5, c4 = i & 31;
        float4 v = ((const float4*)feat)[(size_t)(n0g + r) * 32 + c4];
        v.x = tf32r(v.x); v.y = tf32r(v.y); v.z = tf32r(v.z); v.w = tf32r(v.w);
        ((float4*)(sA + r * AS))[c4] = v;
    }
    // ---- stage W1 k-tile 0 into sH buffer 0 ----
    {
        const float4* src = (const float4*)g_w1r;
        #pragma unroll
        for (int q = 0; q < 8; q++) {
            int i = tid + q * 128;        // 1024 float4 = 8x512
            int r = i >> 7, c4 = i & 127;
            ((float4*)(sH + r * HS))[c4] = src[i];
        }
    }
    __syncthreads();

    // ---- GEMM1: [16,128] @ [128,512], warp w owns cols [w*128, w*128+128) ----
    wmma::fragment<wmma::accumulator, 16, 16, 8, float> c1[8];
    #pragma unroll
    for (int j = 0; j < 8; j++) wmma::fill_fragment(c1[j], 0.0f);

    const int n0 = w * 128;
    for (int kt = 0; kt < 16; kt++) {
        const float* cur = sH + (kt & 1) * (8 * HS);

        wmma::fragment<wmma::matrix_a, 16, 16, 8, wmma::precision::tf32, wmma::row_major> a;
        wmma::load_matrix_sync(a, sA + kt * 8, AS);

        #pragma unroll
        for (int j = 0; j < 8; j++) {
            wmma::fragment<wmma::matrix_b, 16, 16, 8, wmma::precision::tf32, wmma::row_major> b;
            wmma::load_matrix_sync(b, cur + n0 + j * 16, HS);
            wmma::mma_sync(c1[j], a, b, c1[j]);
        }

        if (kt < 15) {
            float* nxt = sH + ((kt + 1) & 1) * (8 * HS);
            const float4* src = (const float4*)g_w1r + (kt + 1) * 1024;
            #pragma unroll
            for (int q = 0; q < 8; q++) {
                int i = tid + q * 128;
                int r = i >> 7, c4 = i & 127;
                ((float4*)(nxt + r * HS))[c4] = src[i];
            }
        }
        __syncthreads();
    }

    // ---- h_raw -> sH as h1 region (stride HS) ----
    #pragma unroll
    for (int j = 0; j < 8; j++)
        wmma::store_matrix_sync(sH + n0 + j * 16, c1[j], HS, wmma::mem_row_major);
    __syncthreads();

    // ---- + E[label], LayerNorm(512), *g1+be1, relu, tf32 round (in place) ----
    #pragma unroll
    for (int i = 0; i < 4; i++) {
        int r = w * 4 + i;
        const float* Ep = g_E + __ldg(&labels[n0g + r]) * 512;
        float vals[16];
        float s = 0.f;
        #pragma unroll
        for (int jj = 0; jj < 16; jj++) {
            int col = cl + 32 * jj;
            vals[jj] = sH[r * HS + col] + __ldg(&Ep[col]);
            s += vals[jj];
        }
        float mu = warp_sum(s) * (1.0f / 512.0f);
        float v = 0.f;
        #pragma unroll
        for (int jj = 0; jj < 16; jj++) {
            float d = vals[jj] - mu;
            v += d * d;
        }
        float rstd = rsqrtf(warp_sum(v) * (1.0f / 512.0f) + 1e-5f);
        #pragma unroll
        for (int jj = 0; jj < 16; jj++) {
            int col = cl + 32 * jj;
            float x = (vals[jj] - mu) * rstd * __ldg(&g1[col]) + __ldg(&be1[col]);
            sH[r * HS + col] = tf32r(fmaxf(x, 0.f));
        }
    }

    // ---- GEMM2: [16,512] @ [512,128], warp w owns cols [w*32, w*32+32) ----
    wmma::fragment<wmma::accumulator, 16, 16, 8, float> c2[2];
    wmma::fill_fragment(c2[0], 0.0f);
    wmma::fill_fragment(c2[1], 0.0f);

    const int n02 = w * 32;
    for (int kt = 0; kt < 32; kt++) {
        __syncthreads();
        const float4* src = (const float4*)g_w2r + kt * 512;
        #pragma unroll
        for (int q = 0; q < 4; q++) {
            int i = tid + q * 128;        // 512 float4 = 16x128
            int r = i >> 5, c4 = i & 31;
            ((float4*)(sA + r * AS))[c4] = src[i];
        }
        __syncthreads();

        #pragma unroll
        for (int ks = 0; ks < 2; ks++) {
            wmma::fragment<wmma::matrix_a, 16, 16, 8, wmma::precision::tf32, wmma::row_major> a2;
            wmma::load_matrix_sync(a2, sH + kt * 16 + ks * 8, HS);
            #pragma unroll
            for (int j = 0; j < 2; j++) {
                wmma::fragment<wmma::matrix_b, 16, 16, 8, wmma::precision::tf32, wmma::row_major> b;
                wmma::load_matrix_sync(b, sA + (ks * 8) * AS + n02 + j * 16, AS);
                wmma::mma_sync(c2[j], a2, b, c2[j]);
            }
        }
    }
    __syncthreads();

    // ---- epilogue: stage C2 to sA (16x128), +b2, *ns, store y ----
    #pragma unroll
    for (int j = 0; j < 2; j++)
        wmma::store_matrix_sync(sA + n02 + j * 16, c2[j], 128, wmma::mem_row_major);
    __syncthreads();

    for (int i = tid; i < 2048; i += 128) {
        int r = i >> 7, col = i & 127;
        int row = n0g + r;
        g_y[(size_t)row * 128 + col] = (sA[i] + __ldg(&b2[col])) * g_ns[row];
    }
}

// ------------------------------------------------------------------
// Scatter: one warp per edge. Lane l moves float4 chunk l of the 128-float row.
__global__ void __launch_bounds__(256) scatter_kernel(
    const int* __restrict__ src, const int* __restrict__ dst)
{
    int gw = (blockIdx.x * 256 + threadIdx.x) >> 5;
    int lane = threadIdx.x & 31;
    if (gw >= EE) return;
    int s = src[gw];
    int d = dst[gw];
    float4 v = ((const float4*)(g_y + (size_t)s * 128))[lane];
    float* ap = g_agg + (size_t)d * 128 + lane * 4;
    asm volatile("red.global.add.v4.f32 [%0], {%1,%2,%3,%4};"
                 :: "l"(ap), "f"(v.x), "f"(v.y), "f"(v.z), "f"(v.w)
                 : "memory");
}

// ------------------------------------------------------------------
// Conv transform on tf32 wmma: z = relu((agg * nd) @ Wc + bc); layer1 *ns -> g_y,
// layer2 -> d_out.  32 rows/block (exact: 100000 = 32*3125), 256 threads (8 warps,
// 2m x 4n), Wc k-tiles (16x128) register-prefetch double-buffered, 1 barrier/iter.
// Static smem 34816 B.
__global__ void __launch_bounds__(256) conv_kernel(
    const float* __restrict__ bc, float* __restrict__ out_ext,
    int which, int to_y)
{
    __shared__ float sA[32 * AS];      // 17408 B (A tile, then epilogue)
    __shared__ float sW[2][16 * AS];   // 2 x 8704 B

    const float* Wcr = which ? g_wc1r : g_wc0r;
    const int tid = threadIdx.x;
    const int w   = tid >> 5;
    const int wm  = w & 1;             // m-group: 16 rows
    const int wn  = w >> 1;            // n-group: 32 cols
    const int n0  = blockIdx.x * 32;

    // ---- load agg tile [32][128] * nd, tf32-rounded ----
    #pragma unroll
    for (int q = 0; q < 4; q++) {
        int i = tid + q * 256;          // 1024 float4 = 32x128
        int r = i >> 5, c4 = i & 31;
        float4 v = ((const float4*)g_agg)[(size_t)(n0 + r) * 32 + c4];
        float ndv = g_nd[n0 + r];
        v.x = tf32r(v.x * ndv); v.y = tf32r(v.y * ndv);
        v.z = tf32r(v.z * ndv); v.w = tf32r(v.w * ndv);
        ((float4*)(sA + r * AS))[c4] = v;
    }
    // ---- stage Wc k-tile 0 (16x128) ----
    {
        const float4* src = (const float4*)Wcr;
        #pragma unroll
        for (int q = 0; q < 2; q++) {
            int i = tid + q * 256;      // 512 float4
            int r = i >> 5, c4 = i & 31;
            ((float4*)(sW[0] + r * AS))[c4] = src[i];
        }
    }
    __syncthreads();

    wmma::fragment<wmma::accumulator, 16, 16, 8, float> c[2];
    wmma::fill_fragment(c[0], 0.0f);
    wmma::fill_fragment(c[1], 0.0f);

    for (int kt = 0; kt < 8; kt++) {
        float4 pre[2];
        if (kt < 7) {
            const float4* src = (const float4*)Wcr + (kt + 1) * 512;
            #pragma unroll
            for (int q = 0; q < 2; q++) pre[q] = src[tid + q * 256];
        }
        const float* cur = sW[kt & 1];

        #pragma unroll
        for (int ks = 0; ks < 2; ks++) {
            wmma::fragment<wmma::matrix_a, 16, 16, 8, wmma::precision::tf32, wmma::row_major> a;
            wmma::load_matrix_sync(a, sA + (wm * 16) * AS + kt * 16 + ks * 8, AS);
            #pragma unroll
            for (int j = 0; j < 2; j++) {
                wmma::fragment<wmma::matrix_b, 16, 16, 8, wmma::precision::tf32, wmma::row_major> b;
                wmma::load_matrix_sync(b, cur + (ks * 8) * AS + wn * 32 + j * 16, AS);
                wmma::mma_sync(c[j], a, b, c[j]);
            }
        }

        if (kt < 7) {
            float* nxt = sW[(kt + 1) & 1];
            #pragma unroll
            for (int q = 0; q < 2; q++) {
                int i = tid + q * 256;
                int r = i >> 5, c4 = i & 31;
                ((float4*)(nxt + r * AS))[c4] = pre[q];
            }
        }
        __syncthreads();   // written buffer was last read at iter kt-1
    }

    // ---- epilogue: stage C to sA (32x128), +bc, relu, (*ns), store ----
    #pragma unroll
    for (int j = 0; j < 2; j++)
        wmma::store_matrix_sync(sA + (wm * 16) * 128 + wn * 32 + j * 16,
                                c[j], 128, wmma::mem_row_major);
    __syncthreads();

    for (int i = tid; i < 4096; i += 256) {
        int r = i >> 7, col = i & 127;
        int row = n0 + r;
        float z = fmaxf(sA[i] + __ldg(&bc[col]), 0.f);
        if (to_y) g_y[(size_t)row * 128 + col] = z * g_ns[row];
        else      out_ext[(size_t)row * 128 + col] = z;
    }
}

// ------------------------------------------------------------------
extern "C" void kernel_launch(void* const* d_in, const int* in_sizes, int n_in,
                              void* d_out, int out_size)
{
    const float* feat   = (const float*)d_in[0];
    const int*   labels = (const int*)  d_in[1];
    const int*   esrc   = (const int*)  d_in[2];
    const int*   edst   = (const int*)  d_in[3];
    const float* emb    = (const float*)d_in[4];
    const float* W1     = (const float*)d_in[5];
    const float* b1     = (const float*)d_in[6];
    const float* g1     = (const float*)d_in[7];
    const float* be1    = (const float*)d_in[8];
    const float* W2     = (const float*)d_in[9];
    const float* b2     = (const float*)d_in[10];
    const float* Wc0    = (const float*)d_in[11];
    const float* bc0    = (const float*)d_in[12];
    const float* Wc1    = (const float*)d_in[13];
    const float* bc1    = (const float*)d_in[14];
    float* out = (float*)d_out;

    // degrees + norms
    zero_deg_kernel<<<(NN + 255) / 256, 256>>>();
    deg_kernel<<<(EE + 255) / 256, 256>>>(esrc, edst);
    norm_kernel<<<(NN + 255) / 256, 256>>>();

    // one-time weight prep
    round_w_kernel<<<163840 / 256, 256>>>(W1, W2, Wc0, Wc1);
    prep_E_kernel<<<48, 256>>>(emb, W1, b1);

    // fused MLP -> y = mlp(x) * ns
    mlp_kernel<<<NN / 16, 128>>>(feat, labels, g1, be1, b2);

    // layer 1
    zero_agg_kernel<<<NN * FF / 4 / 256, 256>>>();
    scatter_kernel<<<EE * 32 / 256, 256>>>(esrc, edst);
    conv_kernel<<<NN / 32, 256>>>(bc0, nullptr, 0, 1);

    // layer 2
    zero_agg_kernel<<<NN * FF / 4 / 256, 256>>>();
    scatter_kernel<<<EE * 32 / 256, 256>>>(esrc, edst);
    conv_kernel<<<NN / 32, 256>>>(bc1, out, 1, 0);
}

// round 11
// speedup vs baseline: 2.2940x; 1.1111x over previous
// R11 = R10 + CSR gather-aggregate replacing atomic scatter (+ zero_agg removal).
#include <cuda_runtime.h>
#include <mma.h>

using namespace nvcuda;

#define NN 100000
#define EE 1600000
#define FF 128

// smem strides (floats): %32 == 8 residues give conflict-free wmma frag loads
#define AS 136    // feat tile / W2 k-tile / conv tile stride
#define HS 520    // W1 k-tile / h1 stride

// ---- scratch (device globals; ~112 MB) ----
__device__ int   g_deg_out[NN];
__device__ int   g_deg_in[NN];
__device__ float g_ns[NN];
__device__ float g_nd[NN];
__device__ float g_y[NN * FF];       // message buffer: h * ns
__device__ float g_agg[NN * FF];     // aggregation result
__device__ float g_w1r[128 * 512];   // tf32-rounded W1 top half (feat rows)
__device__ float g_w2r[512 * 128];   // tf32-rounded W2
__device__ float g_wc0r[128 * 128];  // tf32-rounded Wc0
__device__ float g_wc1r[128 * 128];  // tf32-rounded Wc1
__device__ float g_E[24 * 512];      // emb @ W1_bot + b1 (full fp32)
__device__ int   g_ptr[NN];          // CSR row starts (by dst)
__device__ int   g_cnt[NN];          // fill cursors
__device__ int   g_csr[EE];          // src ids grouped by dst

__device__ __forceinline__ float tf32r(float v) {
    unsigned int r;
    asm("cvt.rna.tf32.f32 %0, %1;" : "=r"(r) : "f"(v));
    return __uint_as_float(r);
}

// ------------------------------------------------------------------
__global__ void zero_deg_kernel() {
    int i = blockIdx.x * blockDim.x + threadIdx.x;
    if (i < NN) { g_deg_out[i] = 0; g_deg_in[i] = 0; }
}

__global__ void deg_kernel(const int* __restrict__ src, const int* __restrict__ dst) {
    int e = blockIdx.x * blockDim.x + threadIdx.x;
    if (e < EE) {
        atomicAdd(&g_deg_out[src[e]], 1);
        atomicAdd(&g_deg_in[dst[e]], 1);
    }
}

__global__ void norm_kernel() {
    int i = blockIdx.x * blockDim.x + threadIdx.x;
    if (i < NN) {
        int dn = g_deg_out[i];
        int dd = g_deg_in[i];
        g_ns[i] = dn > 0 ? rsqrtf((float)dn) : 0.0f;
        g_nd[i] = dd > 0 ? rsqrtf((float)dd) : 0.0f;
    }
}

__device__ __forceinline__ float warp_sum(float v) {
    #pragma unroll
    for (int o = 16; o > 0; o >>= 1) v += __shfl_xor_sync(0xffffffffu, v, o);
    return v;
}

// ------------------------------------------------------------------
// Exclusive scan of deg_in -> g_ptr (and g_cnt copy). 1 block, 1024 threads,
// each thread owns a contiguous chunk of 98 nodes.
__global__ void __launch_bounds__(1024) scan_kernel()
{
    __shared__ int sS[1024];
    const int C = 98;                     // 1024*98 >= NN
    const int t = threadIdx.x;
    const int start = t * C;

    int sum = 0;
    for (int i = start; i < start + C && i < NN; i++) sum += g_deg_in[i];
    sS[t] = sum;
    __syncthreads();

    // inclusive Hillis-Steele scan over the 1024 chunk sums
    for (int off = 1; off < 1024; off <<= 1) {
        int v = (t >= off) ? sS[t - off] : 0;
        __syncthreads();
        sS[t] += v;
        __syncthreads();
    }

    int excl = (t == 0) ? 0 : sS[t - 1];
    for (int i = start; i < start + C && i < NN; i++) {
        g_ptr[i] = excl;
        g_cnt[i] = excl;
        excl += g_deg_in[i];
    }
}

// Fill CSR: slot per edge via per-node cursor.
__global__ void fill_kernel(const int* __restrict__ src, const int* __restrict__ dst)
{
    int e = blockIdx.x * blockDim.x + threadIdx.x;
    if (e < EE) {
        int slot = atomicAdd(&g_cnt[dst[e]], 1);
        g_csr[slot] = src[e];
    }
}

// Gather-aggregate: one warp per dst node, lane = float4 chunk of the row.
// No atomics; writes g_agg directly (zeroing kernels eliminated).
__global__ void __launch_bounds__(256) gather_kernel()
{
    int n = (blockIdx.x * 256 + threadIdx.x) >> 5;
    int lane = threadIdx.x & 31;
    if (n >= NN) return;
    int p = g_ptr[n];
    int pe = p + g_deg_in[n];

    float4 acc = make_float4(0.f, 0.f, 0.f, 0.f);
    for (int j = p; j < pe; j++) {
        int s = __ldg(&g_csr[j]);                       // warp-broadcast load
        float4 v = ((const float4*)(g_y + (size_t)s * 128))[lane];
        acc.x += v.x; acc.y += v.y; acc.z += v.z; acc.w += v.w;
    }
    ((float4*)(g_agg + (size_t)n * 128))[lane] = acc;
}

// ------------------------------------------------------------------
// Round W1 top half + W2 + Wc0 + Wc1 to tf32 once. 163840 elements.
__global__ void round_w_kernel(const float* __restrict__ W1, const float* __restrict__ W2,
                               const float* __restrict__ Wc0, const float* __restrict__ Wc1)
{
    int i = blockIdx.x * blockDim.x + threadIdx.x;
    if (i < 65536)       g_w1r[i] = tf32r(W1[i]);
    else if (i < 131072) g_w2r[i - 65536] = tf32r(W2[i - 65536]);
    else if (i < 147456) g_wc0r[i - 131072] = tf32r(Wc0[i - 131072]);
    else                 g_wc1r[i - 147456] = tf32r(Wc1[i - 147456]);
}

// E = emb @ W1_bot + b1  (fp32 exact). 24*512 outputs, K=128 each.
__global__ void prep_E_kernel(const float* __restrict__ emb, const float* __restrict__ W1,
                              const float* __restrict__ b1)
{
    int t = blockIdx.x * blockDim.x + threadIdx.x;   // t < 24*512
    int c = t >> 9, j = t & 511;
    float s = __ldg(&b1[j]);
    #pragma unroll 8
    for (int k = 0; k < 128; k++)
        s += emb[c * 128 + k] * W1[(128 + k) * 512 + j];
    g_E[t] = s;
}

// ------------------------------------------------------------------
// Fused MLP (proven R8 shape):
//   h_raw = feat @ W1_top            (tf32 wmma, K=128, W1 double-buffered)
//   h1    = tf32(relu(LN(h_raw + E[label]) * g1 + be1))
//   y     = (h1 @ W2 + b2) * ns      (tf32 wmma, K=512)
// 16 rows/block, 128 threads (4 warps). Static smem 41984 B.
__global__ void __launch_bounds__(128) mlp_kernel(
    const float* __restrict__ feat, const int* __restrict__ labels,
    const float* __restrict__ g1, const float* __restrict__ be1,
    const float* __restrict__ b2)
{
    __shared__ float sA[16 * AS];    // 8704 B
    __shared__ float sH[16 * HS];    // 33280 B

    const int tid = threadIdx.x;
    const int w   = tid >> 5;
    const int cl  = tid & 31;
    const int n0g = blockIdx.x * 16;

    // ---- load feat tile [16][128], rounded to tf32 ----
    for (int q = 0; q < 4; q++) {
        int i = tid + q * 128;            // 512 float4
        int r = i >> 5, c4 = i & 31;
        float4 v = ((const float4*)feat)[(size_t)(n0g + r) * 32 + c4];
        v.x = tf32r(v.x); v.y = tf32r(v.y); v.z = tf32r(v.z); v.w = tf32r(v.w);
        ((float4*)(sA + r * AS))[c4] = v;
    }
    // ---- stage W1 k-tile 0 into sH buffer 0 ----
    {
        const float4* src = (const float4*)g_w1r;
        #pragma unroll
        for (int q = 0; q < 8; q++) {
            int i = tid + q * 128;        // 1024 float4 = 8x512
            int r = i >> 7, c4 = i & 127;
            ((float4*)(sH + r * HS))[c4] = src[i];
        }
    }
    __syncthreads();

    // ---- GEMM1: [16,128] @ [128,512], warp w owns cols [w*128, w*128+128) ----
    wmma::fragment<wmma::accumulator, 16, 16, 8, float> c1[8];
    #pragma unroll
    for (int j = 0; j < 8; j++) wmma::fill_fragment(c1[j], 0.0f);

    const int n0 = w * 128;
    for (int kt = 0; kt < 16; kt++) {
        const float* cur = sH + (kt & 1) * (8 * HS);

        wmma::fragment<wmma::matrix_a, 16, 16, 8, wmma::precision::tf32, wmma::row_major> a;
        wmma::load_matrix_sync(a, sA + kt * 8, AS);

        #pragma unroll
        for (int j = 0; j < 8; j++) {
            wmma::fragment<wmma::matrix_b, 16, 16, 8, wmma::precision::tf32, wmma::row_major> b;
            wmma::load_matrix_sync(b, cur + n0 + j * 16, HS);
            wmma::mma_sync(c1[j], a, b, c1[j]);
        }

        if (kt < 15) {
            float* nxt = sH + ((kt + 1) & 1) * (8 * HS);
            const float4* src = (const float4*)g_w1r + (kt + 1) * 1024;
            #pragma unroll
            for (int q = 0; q < 8; q++) {
                int i = tid + q * 128;
                int r = i >> 7, c4 = i & 127;
                ((float4*)(nxt + r * HS))[c4] = src[i];
            }
        }
        __syncthreads();
    }

    // ---- h_raw -> sH as h1 region (stride HS) ----
    #pragma unroll
    for (int j = 0; j < 8; j++)
        wmma::store_matrix_sync(sH + n0 + j * 16, c1[j], HS, wmma::mem_row_major);
    __syncthreads();

    // ---- + E[label], LayerNorm(512), *g1+be1, relu, tf32 round (in place) ----
    #pragma unroll
    for (int i = 0; i < 4; i++) {
        int r = w * 4 + i;
        const float* Ep = g_E + __ldg(&labels[n0g + r]) * 512;
        float vals[16];
        float s = 0.f;
        #pragma unroll
        for (int jj = 0; jj < 16; jj++) {
            int col = cl + 32 * jj;
            vals[jj] = sH[r * HS + col] + __ldg(&Ep[col]);
            s += vals[jj];
        }
        float mu = warp_sum(s) * (1.0f / 512.0f);
        float v = 0.f;
        #pragma unroll
        for (int jj = 0; jj < 16; jj++) {
            float d = vals[jj] - mu;
            v += d * d;
        }
        float rstd = rsqrtf(warp_sum(v) * (1.0f / 512.0f) + 1e-5f);
        #pragma unroll
        for (int jj = 0; jj < 16; jj++) {
            int col = cl + 32 * jj;
            float x = (vals[jj] - mu) * rstd * __ldg(&g1[col]) + __ldg(&be1[col]);
            sH[r * HS + col] = tf32r(fmaxf(x, 0.f));
        }
    }

    // ---- GEMM2: [16,512] @ [512,128], warp w owns cols [w*32, w*32+32) ----
    wmma::fragment<wmma::accumulator, 16, 16, 8, float> c2[2];
    wmma::fill_fragment(c2[0], 0.0f);
    wmma::fill_fragment(c2[1], 0.0f);

    const int n02 = w * 32;
    for (int kt = 0; kt < 32; kt++) {
        __syncthreads();
        const float4* src = (const float4*)g_w2r + kt * 512;
        #pragma unroll
        for (int q = 0; q < 4; q++) {
            int i = tid + q * 128;        // 512 float4 = 16x128
            int r = i >> 5, c4 = i & 31;
            ((float4*)(sA + r * AS))[c4] = src[i];
        }
        __syncthreads();

        #pragma unroll
        for (int ks = 0; ks < 2; ks++) {
            wmma::fragment<wmma::matrix_a, 16, 16, 8, wmma::precision::tf32, wmma::row_major> a2;
            wmma::load_matrix_sync(a2, sH + kt * 16 + ks * 8, HS);
            #pragma unroll
            for (int j = 0; j < 2; j++) {
                wmma::fragment<wmma::matrix_b, 16, 16, 8, wmma::precision::tf32, wmma::row_major> b;
                wmma::load_matrix_sync(b, sA + (ks * 8) * AS + n02 + j * 16, AS);
                wmma::mma_sync(c2[j], a2, b, c2[j]);
            }
        }
    }
    __syncthreads();

    // ---- epilogue: stage C2 to sA (16x128), +b2, *ns, store y ----
    #pragma unroll
    for (int j = 0; j < 2; j++)
        wmma::store_matrix_sync(sA + n02 + j * 16, c2[j], 128, wmma::mem_row_major);
    __syncthreads();

    for (int i = tid; i < 2048; i += 128) {
        int r = i >> 7, col = i & 127;
        int row = n0g + r;
        g_y[(size_t)row * 128 + col] = (sA[i] + __ldg(&b2[col])) * g_ns[row];
    }
}

// ------------------------------------------------------------------
// Conv transform on tf32 wmma: z = relu((agg * nd) @ Wc + bc); layer1 *ns -> g_y,
// layer2 -> d_out.  32 rows/block (exact: 100000 = 32*3125), 256 threads (8 warps,
// 2m x 4n), Wc k-tiles (16x128) register-prefetch double-buffered, 1 barrier/iter.
__global__ void __launch_bounds__(256) conv_kernel(
    const float* __restrict__ bc, float* __restrict__ out_ext,
    int which, int to_y)
{
    __shared__ float sA[32 * AS];      // 17408 B (A tile, then epilogue)
    __shared__ float sW[2][16 * AS];   // 2 x 8704 B

    const float* Wcr = which ? g_wc1r : g_wc0r;
    const int tid = threadIdx.x;
    const int w   = tid >> 5;
    const int wm  = w & 1;             // m-group: 16 rows
    const int wn  = w >> 1;            // n-group: 32 cols
    const int n0  = blockIdx.x * 32;

    // ---- load agg tile [32][128] * nd, tf32-rounded ----
    #pragma unroll
    for (int q = 0; q < 4; q++) {
        int i = tid + q * 256;          // 1024 float4 = 32x128
        int r = i >> 5, c4 = i & 31;
        float4 v = ((const float4*)g_agg)[(size_t)(n0 + r) * 32 + c4];
        float ndv = g_nd[n0 + r];
        v.x = tf32r(v.x * ndv); v.y = tf32r(v.y * ndv);
        v.z = tf32r(v.z * ndv); v.w = tf32r(v.w * ndv);
        ((float4*)(sA + r * AS))[c4] = v;
    }
    // ---- stage Wc k-tile 0 (16x128) ----
    {
        const float4* src = (const float4*)Wcr;
        #pragma unroll
        for (int q = 0; q < 2; q++) {
            int i = tid + q * 256;      // 512 float4
            int r = i >> 5, c4 = i & 31;
            ((float4*)(sW[0] + r * AS))[c4] = src[i];
        }
    }
    __syncthreads();

    wmma::fragment<wmma::accumulator, 16, 16, 8, float> c[2];
    wmma::fill_fragment(c[0], 0.0f);
    wmma::fill_fragment(c[1], 0.0f);

    for (int kt = 0; kt < 8; kt++) {
        float4 pre[2];
        if (kt < 7) {
            const float4* src = (const float4*)Wcr + (kt + 1) * 512;
            #pragma unroll
            for (int q = 0; q < 2; q++) pre[q] = src[tid + q * 256];
        }
        const float* cur = sW[kt & 1];

        #pragma unroll
        for (int ks = 0; ks < 2; ks++) {
            wmma::fragment<wmma::matrix_a, 16, 16, 8, wmma::precision::tf32, wmma::row_major> a;
            wmma::load_matrix_sync(a, sA + (wm * 16) * AS + kt * 16 + ks * 8, AS);
            #pragma unroll
            for (int j = 0; j < 2; j++) {
                wmma::fragment<wmma::matrix_b, 16, 16, 8, wmma::precision::tf32, wmma::row_major> b;
                wmma::load_matrix_sync(b, cur + (ks * 8) * AS + wn * 32 + j * 16, AS);
                wmma::mma_sync(c[j], a, b, c[j]);
            }
        }

        if (kt < 7) {
            float* nxt = sW[(kt + 1) & 1];
            #pragma unroll
            for (int q = 0; q < 2; q++) {
                int i = tid + q * 256;
                int r = i >> 5, c4 = i & 31;
                ((float4*)(nxt + r * AS))[c4] = pre[q];
            }
        }
        __syncthreads();   // written buffer was last read at iter kt-1
    }

    // ---- epilogue: stage C to sA (32x128), +bc, relu, (*ns), store ----
    #pragma unroll
    for (int j = 0; j < 2; j++)
        wmma::store_matrix_sync(sA + (wm * 16) * 128 + wn * 32 + j * 16,
                                c[j], 128, wmma::mem_row_major);
    __syncthreads();

    for (int i = tid; i < 4096; i += 256) {
        int r = i >> 7, col = i & 127;
        int row = n0 + r;
        float z = fmaxf(sA[i] + __ldg(&bc[col]), 0.f);
        if (to_y) g_y[(size_t)row * 128 + col] = z * g_ns[row];
        else      out_ext[(size_t)row * 128 + col] = z;
    }
}

// ------------------------------------------------------------------
extern "C" void kernel_launch(void* const* d_in, const int* in_sizes, int n_in,
                              void* d_out, int out_size)
{
    const float* feat   = (const float*)d_in[0];
    const int*   labels = (const int*)  d_in[1];
    const int*   esrc   = (const int*)  d_in[2];
    const int*   edst   = (const int*)  d_in[3];
    const float* emb    = (const float*)d_in[4];
    const float* W1     = (const float*)d_in[5];
    const float* b1     = (const float*)d_in[6];
    const float* g1     = (const float*)d_in[7];
    const float* be1    = (const float*)d_in[8];
    const float* W2     = (const float*)d_in[9];
    const float* b2     = (const float*)d_in[10];
    const float* Wc0    = (const float*)d_in[11];
    const float* bc0    = (const float*)d_in[12];
    const float* Wc1    = (const float*)d_in[13];
    const float* bc1    = (const float*)d_in[14];
    float* out = (float*)d_out;

    // degrees + norms + CSR (by dst)
    zero_deg_kernel<<<(NN + 255) / 256, 256>>>();
    deg_kernel<<<(EE + 255) / 256, 256>>>(esrc, edst);
    norm_kernel<<<(NN + 255) / 256, 256>>>();
    scan_kernel<<<1, 1024>>>();
    fill_kernel<<<(EE + 255) / 256, 256>>>(esrc, edst);

    // one-time weight prep
    round_w_kernel<<<163840 / 256, 256>>>(W1, W2, Wc0, Wc1);
    prep_E_kernel<<<48, 256>>>(emb, W1, b1);

    // fused MLP -> y = mlp(x) * ns
    mlp_kernel<<<NN / 16, 128>>>(feat, labels, g1, be1, b2);

    // layer 1
    gather_kernel<<<(NN * 32 + 255) / 256, 256>>>();
    conv_kernel<<<NN / 32, 256>>>(bc0, nullptr, 0, 1);

    // layer 2
    gather_kernel<<<(NN * 32 + 255) / 256, 256>>>();
    conv_kernel<<<NN / 32, 256>>>(bc1, out, 1, 0);
}

// round 12
// speedup vs baseline: 2.7216x; 1.1864x over previous
// R12 = R11 with scan_kernel deleted: CSR segment offsets assigned via
// warp-aggregated atomicAdd in norm_kernel (segments need not be node-ordered).
#include <cuda_runtime.h>
#include <mma.h>

using namespace nvcuda;

#define NN 100000
#define EE 1600000
#define FF 128

// smem strides (floats): %32 == 8 residues give conflict-free wmma frag loads
#define AS 136    // feat tile / W2 k-tile / conv tile stride
#define HS 520    // W1 k-tile / h1 stride

// ---- scratch (device globals; ~112 MB) ----
__device__ int   g_deg_out[NN];
__device__ int   g_deg_in[NN];
__device__ float g_ns[NN];
__device__ float g_nd[NN];
__device__ float g_y[NN * FF];       // message buffer: h * ns
__device__ float g_agg[NN * FF];     // aggregation result
__device__ float g_w1r[128 * 512];   // tf32-rounded W1 top half (feat rows)
__device__ float g_w2r[512 * 128];   // tf32-rounded W2
__device__ float g_wc0r[128 * 128];  // tf32-rounded Wc0
__device__ float g_wc1r[128 * 128];  // tf32-rounded Wc1
__device__ float g_E[24 * 512];      // emb @ W1_bot + b1 (full fp32)
__device__ int   g_ptr[NN];          // CSR segment starts (disjoint, unordered)
__device__ int   g_cnt[NN];          // fill cursors
__device__ int   g_csr[EE];          // src ids grouped by dst
__device__ int   g_total;            // slot cursor

__device__ __forceinline__ float tf32r(float v) {
    unsigned int r;
    asm("cvt.rna.tf32.f32 %0, %1;" : "=r"(r) : "f"(v));
    return __uint_as_float(r);
}

// ------------------------------------------------------------------
__global__ void zero_deg_kernel() {
    int i = blockIdx.x * blockDim.x + threadIdx.x;
    if (i < NN) { g_deg_out[i] = 0; g_deg_in[i] = 0; }
    if (i == 0) g_total = 0;
}

__global__ void deg_kernel(const int* __restrict__ src, const int* __restrict__ dst) {
    int e = blockIdx.x * blockDim.x + threadIdx.x;
    if (e < EE) {
        atomicAdd(&g_deg_out[src[e]], 1);
        atomicAdd(&g_deg_in[dst[e]], 1);
    }
}

// norms + CSR segment offset assignment (warp-aggregated cursor grab).
// NO early return: all lanes participate in the shfl scan (tail lanes add 0).
__global__ void norm_kernel() {
    int i = blockIdx.x * blockDim.x + threadIdx.x;
    int lane = threadIdx.x & 31;
    bool valid = i < NN;

    int dd = 0;
    if (valid) {
        int dn = g_deg_out[i];
        dd = g_deg_in[i];
        g_ns[i] = dn > 0 ? rsqrtf((float)dn) : 0.0f;
        g_nd[i] = dd > 0 ? rsqrtf((float)dd) : 0.0f;
    }

    // inclusive warp scan of dd
    int incl = dd;
    #pragma unroll
    for (int off = 1; off < 32; off <<= 1) {
        int v = __shfl_up_sync(0xffffffffu, incl, off);
        if (lane >= off) incl += v;
    }
    int wtot = __shfl_sync(0xffffffffu, incl, 31);
    int base = 0;
    if (lane == 31) base = atomicAdd(&g_total, wtot);
    base = __shfl_sync(0xffffffffu, base, 31);

    if (valid) {
        int p = base + incl - dd;   // exclusive within warp
        g_ptr[i] = p;
        g_cnt[i] = p;
    }
}

__device__ __forceinline__ float warp_sum(float v) {
    #pragma unroll
    for (int o = 16; o > 0; o >>= 1) v += __shfl_xor_sync(0xffffffffu, v, o);
    return v;
}

// Fill CSR: slot per edge via per-node cursor.
__global__ void fill_kernel(const int* __restrict__ src, const int* __restrict__ dst)
{
    int e = blockIdx.x * blockDim.x + threadIdx.x;
    if (e < EE) {
        int slot = atomicAdd(&g_cnt[dst[e]], 1);
        g_csr[slot] = src[e];
    }
}

// Gather-aggregate: one warp per dst node, lane = float4 chunk of the row.
__global__ void __launch_bounds__(256) gather_kernel()
{
    int n = (blockIdx.x * 256 + threadIdx.x) >> 5;
    int lane = threadIdx.x & 31;
    if (n >= NN) return;
    int p = g_ptr[n];
    int pe = p + g_deg_in[n];

    float4 acc = make_float4(0.f, 0.f, 0.f, 0.f);
    for (int j = p; j < pe; j++) {
        int s = __ldg(&g_csr[j]);                       // warp-broadcast load
        float4 v = ((const float4*)(g_y + (size_t)s * 128))[lane];
        acc.x += v.x; acc.y += v.y; acc.z += v.z; acc.w += v.w;
    }
    ((float4*)(g_agg + (size_t)n * 128))[lane] = acc;
}

// ------------------------------------------------------------------
// Round W1 top half + W2 + Wc0 + Wc1 to tf32 once. 163840 elements.
__global__ void round_w_kernel(const float* __restrict__ W1, const float* __restrict__ W2,
                               const float* __restrict__ Wc0, const float* __restrict__ Wc1)
{
    int i = blockIdx.x * blockDim.x + threadIdx.x;
    if (i < 65536)       g_w1r[i] = tf32r(W1[i]);
    else if (i < 131072) g_w2r[i - 65536] = tf32r(W2[i - 65536]);
    else if (i < 147456) g_wc0r[i - 131072] = tf32r(Wc0[i - 131072]);
    else                 g_wc1r[i - 147456] = tf32r(Wc1[i - 147456]);
}

// E = emb @ W1_bot + b1  (fp32 exact). 24*512 outputs, K=128 each.
__global__ void prep_E_kernel(const float* __restrict__ emb, const float* __restrict__ W1,
                              const float* __restrict__ b1)
{
    int t = blockIdx.x * blockDim.x + threadIdx.x;   // t < 24*512
    int c = t >> 9, j = t & 511;
    float s = __ldg(&b1[j]);
    #pragma unroll 8
    for (int k = 0; k < 128; k++)
        s += emb[c * 128 + k] * W1[(128 + k) * 512 + j];
    g_E[t] = s;
}

// ------------------------------------------------------------------
// Fused MLP (proven R8 shape):
//   h_raw = feat @ W1_top            (tf32 wmma, K=128, W1 double-buffered)
//   h1    = tf32(relu(LN(h_raw + E[label]) * g1 + be1))
//   y     = (h1 @ W2 + b2) * ns      (tf32 wmma, K=512)
// 16 rows/block, 128 threads (4 warps). Static smem 41984 B.
__global__ void __launch_bounds__(128) mlp_kernel(
    const float* __restrict__ feat, const int* __restrict__ labels,
    const float* __restrict__ g1, const float* __restrict__ be1,
    const float* __restrict__ b2)
{
    __shared__ float sA[16 * AS];    // 8704 B
    __shared__ float sH[16 * HS];    // 33280 B

    const int tid = threadIdx.x;
    const int w   = tid >> 5;
    const int cl  = tid & 31;
    const int n0g = blockIdx.x * 16;

    // ---- load feat tile [16][128], rounded to tf32 ----
    for (int q = 0; q < 4; q++) {
        int i = tid + q * 128;            // 512 float4
        int r = i >> 5, c4 = i & 31;
        float4 v = ((const float4*)feat)[(size_t)(n0g + r) * 32 + c4];
        v.x = tf32r(v.x); v.y = tf32r(v.y); v.z = tf32r(v.z); v.w = tf32r(v.w);
        ((float4*)(sA + r * AS))[c4] = v;
    }
    // ---- stage W1 k-tile 0 into sH buffer 0 ----
    {
        const float4* src = (const float4*)g_w1r;
        #pragma unroll
        for (int q = 0; q < 8; q++) {
            int i = tid + q * 128;        // 1024 float4 = 8x512
            int r = i >> 7, c4 = i & 127;
            ((float4*)(sH + r * HS))[c4] = src[i];
        }
    }
    __syncthreads();

    // ---- GEMM1: [16,128] @ [128,512], warp w owns cols [w*128, w*128+128) ----
    wmma::fragment<wmma::accumulator, 16, 16, 8, float> c1[8];
    #pragma unroll
    for (int j = 0; j < 8; j++) wmma::fill_fragment(c1[j], 0.0f);

    const int n0 = w * 128;
    for (int kt = 0; kt < 16; kt++) {
        const float* cur = sH + (kt & 1) * (8 * HS);

        wmma::fragment<wmma::matrix_a, 16, 16, 8, wmma::precision::tf32, wmma::row_major> a;
        wmma::load_matrix_sync(a, sA + kt * 8, AS);

        #pragma unroll
        for (int j = 0; j < 8; j++) {
            wmma::fragment<wmma::matrix_b, 16, 16, 8, wmma::precision::tf32, wmma::row_major> b;
            wmma::load_matrix_sync(b, cur + n0 + j * 16, HS);
            wmma::mma_sync(c1[j], a, b, c1[j]);
        }

        if (kt < 15) {
            float* nxt = sH + ((kt + 1) & 1) * (8 * HS);
            const float4* src = (const float4*)g_w1r + (kt + 1) * 1024;
            #pragma unroll
            for (int q = 0; q < 8; q++) {
                int i = tid + q * 128;
                int r = i >> 7, c4 = i & 127;
                ((float4*)(nxt + r * HS))[c4] = src[i];
            }
        }
        __syncthreads();
    }

    // ---- h_raw -> sH as h1 region (stride HS) ----
    #pragma unroll
    for (int j = 0; j < 8; j++)
        wmma::store_matrix_sync(sH + n0 + j * 16, c1[j], HS, wmma::mem_row_major);
    __syncthreads();

    // ---- + E[label], LayerNorm(512), *g1+be1, relu, tf32 round (in place) ----
    #pragma unroll
    for (int i = 0; i < 4; i++) {
        int r = w * 4 + i;
        const float* Ep = g_E + __ldg(&labels[n0g + r]) * 512;
        float vals[16];
        float s = 0.f;
        #pragma unroll
        for (int jj = 0; jj < 16; jj++) {
            int col = cl + 32 * jj;
            vals[jj] = sH[r * HS + col] + __ldg(&Ep[col]);
            s += vals[jj];
        }
        float mu = warp_sum(s) * (1.0f / 512.0f);
        float v = 0.f;
        #pragma unroll
        for (int jj = 0; jj < 16; jj++) {
            float d = vals[jj] - mu;
            v += d * d;
        }
        float rstd = rsqrtf(warp_sum(v) * (1.0f / 512.0f) + 1e-5f);
        #pragma unroll
        for (int jj = 0; jj < 16; jj++) {
            int col = cl + 32 * jj;
            float x = (vals[jj] - mu) * rstd * __ldg(&g1[col]) + __ldg(&be1[col]);
            sH[r * HS + col] = tf32r(fmaxf(x, 0.f));
        }
    }

    // ---- GEMM2: [16,512] @ [512,128], warp w owns cols [w*32, w*32+32) ----
    wmma::fragment<wmma::accumulator, 16, 16, 8, float> c2[2];
    wmma::fill_fragment(c2[0], 0.0f);
    wmma::fill_fragment(c2[1], 0.0f);

    const int n02 = w * 32;
    for (int kt = 0; kt < 32; kt++) {
        __syncthreads();
        const float4* src = (const float4*)g_w2r + kt * 512;
        #pragma unroll
        for (int q = 0; q < 4; q++) {
            int i = tid + q * 128;        // 512 float4 = 16x128
            int r = i >> 5, c4 = i & 31;
            ((float4*)(sA + r * AS))[c4] = src[i];
        }
        __syncthreads();

        #pragma unroll
        for (int ks = 0; ks < 2; ks++) {
            wmma::fragment<wmma::matrix_a, 16, 16, 8, wmma::precision::tf32, wmma::row_major> a2;
            wmma::load_matrix_sync(a2, sH + kt * 16 + ks * 8, HS);
            #pragma unroll
            for (int j = 0; j < 2; j++) {
                wmma::fragment<wmma::matrix_b, 16, 16, 8, wmma::precision::tf32, wmma::row_major> b;
                wmma::load_matrix_sync(b, sA + (ks * 8) * AS + n02 + j * 16, AS);
                wmma::mma_sync(c2[j], a2, b, c2[j]);
            }
        }
    }
    __syncthreads();

    // ---- epilogue: stage C2 to sA (16x128), +b2, *ns, store y ----
    #pragma unroll
    for (int j = 0; j < 2; j++)
        wmma::store_matrix_sync(sA + n02 + j * 16, c2[j], 128, wmma::mem_row_major);
    __syncthreads();

    for (int i = tid; i < 2048; i += 128) {
        int r = i >> 7, col = i & 127;
        int row = n0g + r;
        g_y[(size_t)row * 128 + col] = (sA[i] + __ldg(&b2[col])) * g_ns[row];
    }
}

// ------------------------------------------------------------------
// Conv transform on tf32 wmma: z = relu((agg * nd) @ Wc + bc); layer1 *ns -> g_y,
// layer2 -> d_out.  32 rows/block (exact: 100000 = 32*3125), 256 threads (8 warps,
// 2m x 4n), Wc k-tiles (16x128) register-prefetch double-buffered, 1 barrier/iter.
__global__ void __launch_bounds__(256) conv_kernel(
    const float* __restrict__ bc, float* __restrict__ out_ext,
    int which, int to_y)
{
    __shared__ float sA[32 * AS];      // 17408 B (A tile, then epilogue)
    __shared__ float sW[2][16 * AS];   // 2 x 8704 B

    const float* Wcr = which ? g_wc1r : g_wc0r;
    const int tid = threadIdx.x;
    const int w   = tid >> 5;
    const int wm  = w & 1;             // m-group: 16 rows
    const int wn  = w >> 1;            // n-group: 32 cols
    const int n0  = blockIdx.x * 32;

    // ---- load agg tile [32][128] * nd, tf32-rounded ----
    #pragma unroll
    for (int q = 0; q < 4; q++) {
        int i = tid + q * 256;          // 1024 float4 = 32x128
        int r = i >> 5, c4 = i & 31;
        float4 v = ((const float4*)g_agg)[(size_t)(n0 + r) * 32 + c4];
        float ndv = g_nd[n0 + r];
        v.x = tf32r(v.x * ndv); v.y = tf32r(v.y * ndv);
        v.z = tf32r(v.z * ndv); v.w = tf32r(v.w * ndv);
        ((float4*)(sA + r * AS))[c4] = v;
    }
    // ---- stage Wc k-tile 0 (16x128) ----
    {
        const float4* src = (const float4*)Wcr;
        #pragma unroll
        for (int q = 0; q < 2; q++) {
            int i = tid + q * 256;      // 512 float4
            int r = i >> 5, c4 = i & 31;
            ((float4*)(sW[0] + r * AS))[c4] = src[i];
        }
    }
    __syncthreads();

    wmma::fragment<wmma::accumulator, 16, 16, 8, float> c[2];
    wmma::fill_fragment(c[0], 0.0f);
    wmma::fill_fragment(c[1], 0.0f);

    for (int kt = 0; kt < 8; kt++) {
        float4 pre[2];
        if (kt < 7) {
            const float4* src = (const float4*)Wcr + (kt + 1) * 512;
            #pragma unroll
            for (int q = 0; q < 2; q++) pre[q] = src[tid + q * 256];
        }
        const float* cur = sW[kt & 1];

        #pragma unroll
        for (int ks = 0; ks < 2; ks++) {
            wmma::fragment<wmma::matrix_a, 16, 16, 8, wmma::precision::tf32, wmma::row_major> a;
            wmma::load_matrix_sync(a, sA + (wm * 16) * AS + kt * 16 + ks * 8, AS);
            #pragma unroll
            for (int j = 0; j < 2; j++) {
                wmma::fragment<wmma::matrix_b, 16, 16, 8, wmma::precision::tf32, wmma::row_major> b;
                wmma::load_matrix_sync(b, cur + (ks * 8) * AS + wn * 32 + j * 16, AS);
                wmma::mma_sync(c[j], a, b, c[j]);
            }
        }

        if (kt < 7) {
            float* nxt = sW[(kt + 1) & 1];
            #pragma unroll
            for (int q = 0; q < 2; q++) {
                int i = tid + q * 256;
                int r = i >> 5, c4 = i & 31;
                ((float4*)(nxt + r * AS))[c4] = pre[q];
            }
        }
        __syncthreads();   // written buffer was last read at iter kt-1
    }

    // ---- epilogue: stage C to sA (32x128), +bc, relu, (*ns), store ----
    #pragma unroll
    for (int j = 0; j < 2; j++)
        wmma::store_matrix_sync(sA + (wm * 16) * 128 + wn * 32 + j * 16,
                                c[j], 128, wmma::mem_row_major);
    __syncthreads();

    for (int i = tid; i < 4096; i += 256) {
        int r = i >> 7, col = i & 127;
        int row = n0 + r;
        float z = fmaxf(sA[i] + __ldg(&bc[col]), 0.f);
        if (to_y) g_y[(size_t)row * 128 + col] = z * g_ns[row];
        else      out_ext[(size_t)row * 128 + col] = z;
    }
}

// ------------------------------------------------------------------
extern "C" void kernel_launch(void* const* d_in, const int* in_sizes, int n_in,
                              void* d_out, int out_size)
{
    const float* feat   = (const float*)d_in[0];
    const int*   labels = (const int*)  d_in[1];
    const int*   esrc   = (const int*)  d_in[2];
    const int*   edst   = (const int*)  d_in[3];
    const float* emb    = (const float*)d_in[4];
    const float* W1     = (const float*)d_in[5];
    const float* b1     = (const float*)d_in[6];
    const float* g1     = (const float*)d_in[7];
    const float* be1    = (const float*)d_in[8];
    const float* W2     = (const float*)d_in[9];
    const float* b2     = (const float*)d_in[10];
    const float* Wc0    = (const float*)d_in[11];
    const float* bc0    = (const float*)d_in[12];
    const float* Wc1    = (const float*)d_in[13];
    const float* bc1    = (const float*)d_in[14];
    float* out = (float*)d_out;

    // degrees + norms + CSR segment offsets (no scan kernel)
    zero_deg_kernel<<<(NN + 255) / 256, 256>>>();
    deg_kernel<<<(EE + 255) / 256, 256>>>(esrc, edst);
    norm_kernel<<<(NN + 255) / 256, 256>>>();
    fill_kernel<<<(EE + 255) / 256, 256>>>(esrc, edst);

    // one-time weight prep
    round_w_kernel<<<163840 / 256, 256>>>(W1, W2, Wc0, Wc1);
    prep_E_kernel<<<48, 256>>>(emb, W1, b1);

    // fused MLP -> y = mlp(x) * ns
    mlp_kernel<<<NN / 16, 128>>>(feat, labels, g1, be1, b2);

    // layer 1
    gather_kernel<<<(NN * 32 + 255) / 256, 256>>>();
    conv_kernel<<<NN / 32, 256>>>(bc0, nullptr, 0, 1);

    // layer 2
    gather_kernel<<<(NN * 32 + 255) / 256, 256>>>();
    conv_kernel<<<NN / 32, 256>>>(bc1, out, 1, 0);
}

// round 13
// speedup vs baseline: 2.7339x; 1.0045x over previous
// R13 = R12 with the fused MLP widened to 32 rows/block (256 thr, 8 warps,
// 2m x 4n warp grid, 84 KB dynamic smem) to halve W1/W2 staging traffic.
#include <cuda_runtime.h>
#include <mma.h>

using namespace nvcuda;

#define NN 100000
#define EE 1600000
#define FF 128

// smem strides (floats): %32 == 8 residues give conflict-free wmma frag loads
#define AS 136    // feat tile / W2 k-tile / conv tile stride
#define HS 520    // W1 k-tile / h1 stride
#define MLP_SMEM_FLOATS (32 * HS + 32 * AS)          // 16640 + 4352 = 20992
#define MLP_SMEM_BYTES  (MLP_SMEM_FLOATS * 4)       // 83968

// ---- scratch (device globals; ~112 MB) ----
__device__ int   g_deg_out[NN];
__device__ int   g_deg_in[NN];
__device__ float g_ns[NN];
__device__ float g_nd[NN];
__device__ float g_y[NN * FF];       // message buffer: h * ns
__device__ float g_agg[NN * FF];     // aggregation result
__device__ float g_w1r[128 * 512];   // tf32-rounded W1 top half (feat rows)
__device__ float g_w2r[512 * 128];   // tf32-rounded W2
__device__ float g_wc0r[128 * 128];  // tf32-rounded Wc0
__device__ float g_wc1r[128 * 128];  // tf32-rounded Wc1
__device__ float g_E[24 * 512];      // emb @ W1_bot + b1 (full fp32)
__device__ int   g_ptr[NN];          // CSR segment starts (disjoint, unordered)
__device__ int   g_cnt[NN];          // fill cursors
__device__ int   g_csr[EE];          // src ids grouped by dst
__device__ int   g_total;            // slot cursor

__device__ __forceinline__ float tf32r(float v) {
    unsigned int r;
    asm("cvt.rna.tf32.f32 %0, %1;" : "=r"(r) : "f"(v));
    return __uint_as_float(r);
}

// ------------------------------------------------------------------
__global__ void zero_deg_kernel() {
    int i = blockIdx.x * blockDim.x + threadIdx.x;
    if (i < NN) { g_deg_out[i] = 0; g_deg_in[i] = 0; }
    if (i == 0) g_total = 0;
}

__global__ void deg_kernel(const int* __restrict__ src, const int* __restrict__ dst) {
    int e = blockIdx.x * blockDim.x + threadIdx.x;
    if (e < EE) {
        atomicAdd(&g_deg_out[src[e]], 1);
        atomicAdd(&g_deg_in[dst[e]], 1);
    }
}

// norms + CSR segment offset assignment (warp-aggregated cursor grab).
__global__ void norm_kernel() {
    int i = blockIdx.x * blockDim.x + threadIdx.x;
    int lane = threadIdx.x & 31;
    bool valid = i < NN;

    int dd = 0;
    if (valid) {
        int dn = g_deg_out[i];
        dd = g_deg_in[i];
        g_ns[i] = dn > 0 ? rsqrtf((float)dn) : 0.0f;
        g_nd[i] = dd > 0 ? rsqrtf((float)dd) : 0.0f;
    }

    int incl = dd;
    #pragma unroll
    for (int off = 1; off < 32; off <<= 1) {
        int v = __shfl_up_sync(0xffffffffu, incl, off);
        if (lane >= off) incl += v;
    }
    int wtot = __shfl_sync(0xffffffffu, incl, 31);
    int base = 0;
    if (lane == 31) base = atomicAdd(&g_total, wtot);
    base = __shfl_sync(0xffffffffu, base, 31);

    if (valid) {
        int p = base + incl - dd;
        g_ptr[i] = p;
        g_cnt[i] = p;
    }
}

__device__ __forceinline__ float warp_sum(float v) {
    #pragma unroll
    for (int o = 16; o > 0; o >>= 1) v += __shfl_xor_sync(0xffffffffu, v, o);
    return v;
}

// Fill CSR: slot per edge via per-node cursor.
__global__ void fill_kernel(const int* __restrict__ src, const int* __restrict__ dst)
{
    int e = blockIdx.x * blockDim.x + threadIdx.x;
    if (e < EE) {
        int slot = atomicAdd(&g_cnt[dst[e]], 1);
        g_csr[slot] = src[e];
    }
}

// Gather-aggregate: one warp per dst node, lane = float4 chunk of the row.
__global__ void __launch_bounds__(256) gather_kernel()
{
    int n = (blockIdx.x * 256 + threadIdx.x) >> 5;
    int lane = threadIdx.x & 31;
    if (n >= NN) return;
    int p = g_ptr[n];
    int pe = p + g_deg_in[n];

    float4 acc = make_float4(0.f, 0.f, 0.f, 0.f);
    for (int j = p; j < pe; j++) {
        int s = __ldg(&g_csr[j]);
        float4 v = ((const float4*)(g_y + (size_t)s * 128))[lane];
        acc.x += v.x; acc.y += v.y; acc.z += v.z; acc.w += v.w;
    }
    ((float4*)(g_agg + (size_t)n * 128))[lane] = acc;
}

// ------------------------------------------------------------------
// Round W1 top half + W2 + Wc0 + Wc1 to tf32 once. 163840 elements.
__global__ void round_w_kernel(const float* __restrict__ W1, const float* __restrict__ W2,
                               const float* __restrict__ Wc0, const float* __restrict__ Wc1)
{
    int i = blockIdx.x * blockDim.x + threadIdx.x;
    if (i < 65536)       g_w1r[i] = tf32r(W1[i]);
    else if (i < 131072) g_w2r[i - 65536] = tf32r(W2[i - 65536]);
    else if (i < 147456) g_wc0r[i - 131072] = tf32r(Wc0[i - 131072]);
    else                 g_wc1r[i - 147456] = tf32r(Wc1[i - 147456]);
}

// E = emb @ W1_bot + b1  (fp32 exact). 24*512 outputs, K=128 each.
__global__ void prep_E_kernel(const float* __restrict__ emb, const float* __restrict__ W1,
                              const float* __restrict__ b1)
{
    int t = blockIdx.x * blockDim.x + threadIdx.x;
    int c = t >> 9, j = t & 511;
    float s = __ldg(&b1[j]);
    #pragma unroll 8
    for (int k = 0; k < 128; k++)
        s += emb[c * 128 + k] * W1[(128 + k) * 512 + j];
    g_E[t] = s;
}

// ------------------------------------------------------------------
// Fused MLP, 32 rows/block, 256 threads (8 warps, 2m x 4n):
//   h_raw = feat @ W1_top            (tf32 wmma, K=128, W1 double-buffered)
//   h1    = tf32(relu(LN(h_raw + E[label]) * g1 + be1))
//   y     = (h1 @ W2 + b2) * ns      (tf32 wmma, K=512)
// Dynamic smem 83968 B: sH = 32 x HS (W1 double-buffer 2x8xHS, then h1),
//                       sA = 32 x AS (feat tile; then W2 k-tiles; then epilogue).
__global__ void __launch_bounds__(256) mlp_kernel(
    const float* __restrict__ feat, const int* __restrict__ labels,
    const float* __restrict__ g1, const float* __restrict__ be1,
    const float* __restrict__ b2)
{
    extern __shared__ float sm[];
    float* sH = sm;               // 16640 floats
    float* sA = sm + 32 * HS;     // 4352 floats

    const int tid = threadIdx.x;
    const int w   = tid >> 5;
    const int cl  = tid & 31;
    const int wm  = w & 1;        // m-group: rows wm*16 .. +16
    const int wn  = w >> 1;       // n-group 0..3
    const int n0g = blockIdx.x * 32;
    const int row0 = wm * 16;

    // ---- load feat tile [32][128], rounded to tf32 ----
    #pragma unroll
    for (int q = 0; q < 4; q++) {
        int i = tid + q * 256;            // 1024 float4
        int r = i >> 5, c4 = i & 31;
        float4 v = ((const float4*)feat)[(size_t)(n0g + r) * 32 + c4];
        v.x = tf32r(v.x); v.y = tf32r(v.y); v.z = tf32r(v.z); v.w = tf32r(v.w);
        ((float4*)(sA + r * AS))[c4] = v;
    }
    // ---- stage W1 k-tile 0 into sH buffer 0 ----
    {
        const float4* src = (const float4*)g_w1r;
        #pragma unroll
        for (int q = 0; q < 4; q++) {
            int i = tid + q * 256;        // 1024 float4 = 8x512
            int r = i >> 7, c4 = i & 127;
            ((float4*)(sH + r * HS))[c4] = src[i];
        }
    }
    __syncthreads();

    // ---- GEMM1: [32,128] @ [128,512]; warp (wm,wn): rows row0.., cols wn*128.. ----
    wmma::fragment<wmma::accumulator, 16, 16, 8, float> c1[8];
    #pragma unroll
    for (int j = 0; j < 8; j++) wmma::fill_fragment(c1[j], 0.0f);

    const int n0 = wn * 128;
    for (int kt = 0; kt < 16; kt++) {
        const float* cur = sH + (kt & 1) * (8 * HS);

        wmma::fragment<wmma::matrix_a, 16, 16, 8, wmma::precision::tf32, wmma::row_major> a;
        wmma::load_matrix_sync(a, sA + row0 * AS + kt * 8, AS);

        #pragma unroll
        for (int j = 0; j < 8; j++) {
            wmma::fragment<wmma::matrix_b, 16, 16, 8, wmma::precision::tf32, wmma::row_major> b;
            wmma::load_matrix_sync(b, cur + n0 + j * 16, HS);
            wmma::mma_sync(c1[j], a, b, c1[j]);
        }

        if (kt < 15) {
            float* nxt = sH + ((kt + 1) & 1) * (8 * HS);
            const float4* src = (const float4*)g_w1r + (kt + 1) * 1024;
            #pragma unroll
            for (int q = 0; q < 4; q++) {
                int i = tid + q * 256;
                int r = i >> 7, c4 = i & 127;
                ((float4*)(nxt + r * HS))[c4] = src[i];
            }
        }
        __syncthreads();
    }

    // ---- h_raw -> sH rows 0..31 (stride HS) ----
    #pragma unroll
    for (int j = 0; j < 8; j++)
        wmma::store_matrix_sync(sH + row0 * HS + n0 + j * 16, c1[j], HS, wmma::mem_row_major);
    __syncthreads();

    // ---- + E[label], LayerNorm(512), *g1+be1, relu, tf32 round (in place) ----
    #pragma unroll
    for (int i = 0; i < 4; i++) {
        int r = w * 4 + i;                       // 8 warps x 4 = 32 rows
        const float* Ep = g_E + __ldg(&labels[n0g + r]) * 512;
        float vals[16];
        float s = 0.f;
        #pragma unroll
        for (int jj = 0; jj < 16; jj++) {
            int col = cl + 32 * jj;
            vals[jj] = sH[r * HS + col] + __ldg(&Ep[col]);
            s += vals[jj];
        }
        float mu = warp_sum(s) * (1.0f / 512.0f);
        float v = 0.f;
        #pragma unroll
        for (int jj = 0; jj < 16; jj++) {
            float d = vals[jj] - mu;
            v += d * d;
        }
        float rstd = rsqrtf(warp_sum(v) * (1.0f / 512.0f) + 1e-5f);
        #pragma unroll
        for (int jj = 0; jj < 16; jj++) {
            int col = cl + 32 * jj;
            float x = (vals[jj] - mu) * rstd * __ldg(&g1[col]) + __ldg(&be1[col]);
            sH[r * HS + col] = tf32r(fmaxf(x, 0.f));
        }
    }

    // ---- GEMM2: [32,512] @ [512,128]; warp (wm,wn): rows row0.., cols wn*32.. ----
    wmma::fragment<wmma::accumulator, 16, 16, 8, float> c2[2];
    wmma::fill_fragment(c2[0], 0.0f);
    wmma::fill_fragment(c2[1], 0.0f);

    const int n02 = wn * 32;
    for (int kt = 0; kt < 32; kt++) {
        __syncthreads();
        const float4* src = (const float4*)g_w2r + kt * 512;
        #pragma unroll
        for (int q = 0; q < 2; q++) {
            int i = tid + q * 256;        // 512 float4 = 16x128
            int r = i >> 5, c4 = i & 31;
            ((float4*)(sA + r * AS))[c4] = src[i];
        }
        __syncthreads();

        #pragma unroll
        for (int ks = 0; ks < 2; ks++) {
            wmma::fragment<wmma::matrix_a, 16, 16, 8, wmma::precision::tf32, wmma::row_major> a2;
            wmma::load_matrix_sync(a2, sH + row0 * HS + kt * 16 + ks * 8, HS);
            #pragma unroll
            for (int j = 0; j < 2; j++) {
                wmma::fragment<wmma::matrix_b, 16, 16, 8, wmma::precision::tf32, wmma::row_major> b;
                wmma::load_matrix_sync(b, sA + (ks * 8) * AS + n02 + j * 16, AS);
                wmma::mma_sync(c2[j], a2, b, c2[j]);
            }
        }
    }
    __syncthreads();

    // ---- epilogue: stage C2 to sA (32x128), +b2, *ns, store y ----
    #pragma unroll
    for (int j = 0; j < 2; j++)
        wmma::store_matrix_sync(sA + row0 * 128 + n02 + j * 16, c2[j], 128, wmma::mem_row_major);
    __syncthreads();

    for (int i = tid; i < 4096; i += 256) {
        int r = i >> 7, col = i & 127;
        int row = n0g + r;
        g_y[(size_t)row * 128 + col] = (sA[i] + __ldg(&b2[col])) * g_ns[row];
    }
}

// ------------------------------------------------------------------
// Conv transform on tf32 wmma (unchanged from R12).
__global__ void __launch_bounds__(256) conv_kernel(
    const float* __restrict__ bc, float* __restrict__ out_ext,
    int which, int to_y)
{
    __shared__ float sA[32 * AS];      // 17408 B (A tile, then epilogue)
    __shared__ float sW[2][16 * AS];   // 2 x 8704 B

    const float* Wcr = which ? g_wc1r : g_wc0r;
    const int tid = threadIdx.x;
    const int w   = tid >> 5;
    const int wm  = w & 1;
    const int wn  = w >> 1;
    const int n0  = blockIdx.x * 32;

    #pragma unroll
    for (int q = 0; q < 4; q++) {
        int i = tid + q * 256;
        int r = i >> 5, c4 = i & 31;
        float4 v = ((const float4*)g_agg)[(size_t)(n0 + r) * 32 + c4];
        float ndv = g_nd[n0 + r];
        v.x = tf32r(v.x * ndv); v.y = tf32r(v.y * ndv);
        v.z = tf32r(v.z * ndv); v.w = tf32r(v.w * ndv);
        ((float4*)(sA + r * AS))[c4] = v;
    }
    {
        const float4* src = (const float4*)Wcr;
        #pragma unroll
        for (int q = 0; q < 2; q++) {
            int i = tid + q * 256;
            int r = i >> 5, c4 = i & 31;
            ((float4*)(sW[0] + r * AS))[c4] = src[i];
        }
    }
    __syncthreads();

    wmma::fragment<wmma::accumulator, 16, 16, 8, float> c[2];
    wmma::fill_fragment(c[0], 0.0f);
    wmma::fill_fragment(c[1], 0.0f);

    for (int kt = 0; kt < 8; kt++) {
        float4 pre[2];
        if (kt < 7) {
            const float4* src = (const float4*)Wcr + (kt + 1) * 512;
            #pragma unroll
            for (int q = 0; q < 2; q++) pre[q] = src[tid + q * 256];
        }
        const float* cur = sW[kt & 1];

        #pragma unroll
        for (int ks = 0; ks < 2; ks++) {
            wmma::fragment<wmma::matrix_a, 16, 16, 8, wmma::precision::tf32, wmma::row_major> a;
            wmma::load_matrix_sync(a, sA + (wm * 16) * AS + kt * 16 + ks * 8, AS);
            #pragma unroll
            for (int j = 0; j < 2; j++) {
                wmma::fragment<wmma::matrix_b, 16, 16, 8, wmma::precision::tf32, wmma::row_major> b;
                wmma::load_matrix_sync(b, cur + (ks * 8) * AS + wn * 32 + j * 16, AS);
                wmma::mma_sync(c[j], a, b, c[j]);
            }
        }

        if (kt < 7) {
            float* nxt = sW[(kt + 1) & 1];
            #pragma unroll
            for (int q = 0; q < 2; q++) {
                int i = tid + q * 256;
                int r = i >> 5, c4 = i & 31;
                ((float4*)(nxt + r * AS))[c4] = pre[q];
            }
        }
        __syncthreads();
    }

    #pragma unroll
    for (int j = 0; j < 2; j++)
        wmma::store_matrix_sync(sA + (wm * 16) * 128 + wn * 32 + j * 16,
                                c[j], 128, wmma::mem_row_major);
    __syncthreads();

    for (int i = tid; i < 4096; i += 256) {
        int r = i >> 7, col = i & 127;
        int row = n0 + r;
        float z = fmaxf(sA[i] + __ldg(&bc[col]), 0.f);
        if (to_y) g_y[(size_t)row * 128 + col] = z * g_ns[row];
        else      out_ext[(size_t)row * 128 + col] = z;
    }
}

// ------------------------------------------------------------------
extern "C" void kernel_launch(void* const* d_in, const int* in_sizes, int n_in,
                              void* d_out, int out_size)
{
    const float* feat   = (const float*)d_in[0];
    const int*   labels = (const int*)  d_in[1];
    const int*   esrc   = (const int*)  d_in[2];
    const int*   edst   = (const int*)  d_in[3];
    const float* emb    = (const float*)d_in[4];
    const float* W1     = (const float*)d_in[5];
    const float* b1     = (const float*)d_in[6];
    const float* g1     = (const float*)d_in[7];
    const float* be1    = (const float*)d_in[8];
    const float* W2     = (const float*)d_in[9];
    const float* b2     = (const float*)d_in[10];
    const float* Wc0    = (const float*)d_in[11];
    const float* bc0    = (const float*)d_in[12];
    const float* Wc1    = (const float*)d_in[13];
    const float* bc1    = (const float*)d_in[14];
    float* out = (float*)d_out;

    cudaFuncSetAttribute(mlp_kernel, cudaFuncAttributeMaxDynamicSharedMemorySize,
                         MLP_SMEM_BYTES);

    // degrees + norms + CSR segment offsets
    zero_deg_kernel<<<(NN + 255) / 256, 256>>>();
    deg_kernel<<<(EE + 255) / 256, 256>>>(esrc, edst);
    norm_kernel<<<(NN + 255) / 256, 256>>>();
    fill_kernel<<<(EE + 255) / 256, 256>>>(esrc, edst);

    // one-time weight prep
    round_w_kernel<<<163840 / 256, 256>>>(W1, W2, Wc0, Wc1);
    prep_E_kernel<<<48, 256>>>(emb, W1, b1);

    // fused MLP -> y = mlp(x) * ns
    mlp_kernel<<<NN / 32, 256, MLP_SMEM_BYTES>>>(feat, labels, g1, be1, b2);

    // layer 1
    gather_kernel<<<(NN * 32 + 255) / 256, 256>>>();
    conv_kernel<<<NN / 32, 256>>>(bc0, nullptr, 0, 1);

    // layer 2
    gather_kernel<<<(NN * 32 + 255) / 256, 256>>>();
    conv_kernel<<<NN / 32, 256>>>(bc1, out, 1, 0);
}

// round 15
// speedup vs baseline: 2.7656x; 1.0116x over previous
// R15 = R14 resubmission (container-level infra failure, no harness evidence;
// re-running the identical experiment per R10 precedent).
// Delta vs R13 (passing, 897 us): mlp moved to launch #4 for ncu capture,
// round_w/prep_E merged into deg/norm kernels, gather edge-loop unrolled x4.
#include <cuda_runtime.h>
#include <mma.h>

using namespace nvcuda;

#define NN 100000
#define EE 1600000
#define FF 128

#define AS 136    // feat tile / W2 k-tile / conv tile stride
#define HS 520    // W1 k-tile / h1 stride
#define MLP_SMEM_FLOATS (32 * HS + 32 * AS)
#define MLP_SMEM_BYTES  (MLP_SMEM_FLOATS * 4)       // 83968

// ---- scratch (device globals; ~112 MB) ----
__device__ int   g_deg_out[NN];
__device__ int   g_deg_in[NN];
__device__ float g_ns[NN];
__device__ float g_nd[NN];
__device__ float g_y[NN * FF];
__device__ float g_agg[NN * FF];
__device__ float g_w1r[128 * 512];
__device__ float g_w2r[512 * 128];
__device__ float g_wc0r[128 * 128];
__device__ float g_wc1r[128 * 128];
__device__ float g_E[24 * 512];
__device__ int   g_ptr[NN];
__device__ int   g_cnt[NN];
__device__ int   g_csr[EE];
__device__ int   g_total;

__device__ __forceinline__ float tf32r(float v) {
    unsigned int r;
    asm("cvt.rna.tf32.f32 %0, %1;" : "=r"(r) : "f"(v));
    return __uint_as_float(r);
}

// ------------------------------------------------------------------
__global__ void zero_deg_kernel() {
    int i = blockIdx.x * blockDim.x + threadIdx.x;
    if (i < NN) { g_deg_out[i] = 0; g_deg_in[i] = 0; }
    if (i == 0) g_total = 0;
}

// degrees + (merged) one-time tf32 rounding of W1-top/W2/Wc0/Wc1.
__global__ void deg_round_kernel(const int* __restrict__ src, const int* __restrict__ dst,
                                 const float* __restrict__ W1, const float* __restrict__ W2,
                                 const float* __restrict__ Wc0, const float* __restrict__ Wc1)
{
    int e = blockIdx.x * blockDim.x + threadIdx.x;
    if (e < EE) {
        atomicAdd(&g_deg_out[src[e]], 1);
        atomicAdd(&g_deg_in[dst[e]], 1);
    }
    if (e < 163840) {
        int i = e;
        if (i < 65536)       g_w1r[i] = tf32r(W1[i]);
        else if (i < 131072) g_w2r[i - 65536] = tf32r(W2[i - 65536]);
        else if (i < 147456) g_wc0r[i - 131072] = tf32r(Wc0[i - 131072]);
        else                 g_wc1r[i - 147456] = tf32r(Wc1[i - 147456]);
    }
}

// norms + CSR segment offsets (warp-aggregated cursor grab) + (merged) E table.
__global__ void norm_prep_kernel(const float* __restrict__ emb,
                                 const float* __restrict__ W1,
                                 const float* __restrict__ b1)
{
    int i = blockIdx.x * blockDim.x + threadIdx.x;
    int lane = threadIdx.x & 31;
    bool valid = i < NN;

    int dd = 0;
    if (valid) {
        int dn = g_deg_out[i];
        dd = g_deg_in[i];
        g_ns[i] = dn > 0 ? rsqrtf((float)dn) : 0.0f;
        g_nd[i] = dd > 0 ? rsqrtf((float)dd) : 0.0f;
    }

    int incl = dd;
    #pragma unroll
    for (int off = 1; off < 32; off <<= 1) {
        int v = __shfl_up_sync(0xffffffffu, incl, off);
        if (lane >= off) incl += v;
    }
    int wtot = __shfl_sync(0xffffffffu, incl, 31);
    int base = 0;
    if (lane == 31) base = atomicAdd(&g_total, wtot);
    base = __shfl_sync(0xffffffffu, base, 31);

    if (valid) {
        int p = base + incl - dd;
        g_ptr[i] = p;
        g_cnt[i] = p;
    }

    // E = emb @ W1_bot + b1 (first 12288 threads)
    if (i < 24 * 512) {
        int c = i >> 9, j = i & 511;
        float s = __ldg(&b1[j]);
        #pragma unroll 8
        for (int k = 0; k < 128; k++)
            s += emb[c * 128 + k] * W1[(128 + k) * 512 + j];
        g_E[i] = s;
    }
}

__device__ __forceinline__ float warp_sum(float v) {
    #pragma unroll
    for (int o = 16; o > 0; o >>= 1) v += __shfl_xor_sync(0xffffffffu, v, o);
    return v;
}

// Fill CSR: slot per edge via per-node cursor.
__global__ void fill_kernel(const int* __restrict__ src, const int* __restrict__ dst)
{
    int e = blockIdx.x * blockDim.x + threadIdx.x;
    if (e < EE) {
        int slot = atomicAdd(&g_cnt[dst[e]], 1);
        g_csr[slot] = src[e];
    }
}

// Gather-aggregate: one warp per dst node; edge loop unrolled x4 (MLP=4).
__global__ void __launch_bounds__(256) gather_kernel()
{
    int n = (blockIdx.x * 256 + threadIdx.x) >> 5;
    int lane = threadIdx.x & 31;
    if (n >= NN) return;
    int p = g_ptr[n];
    int pe = p + g_deg_in[n];

    float4 acc = make_float4(0.f, 0.f, 0.f, 0.f);
    int j = p;
    for (; j + 4 <= pe; j += 4) {
        int s0 = __ldg(&g_csr[j]);
        int s1 = __ldg(&g_csr[j + 1]);
        int s2 = __ldg(&g_csr[j + 2]);
        int s3 = __ldg(&g_csr[j + 3]);
        float4 v0 = ((const float4*)(g_y + (size_t)s0 * 128))[lane];
        float4 v1 = ((const float4*)(g_y + (size_t)s1 * 128))[lane];
        float4 v2 = ((const float4*)(g_y + (size_t)s2 * 128))[lane];
        float4 v3 = ((const float4*)(g_y + (size_t)s3 * 128))[lane];
        acc.x += v0.x + v1.x + v2.x + v3.x;
        acc.y += v0.y + v1.y + v2.y + v3.y;
        acc.z += v0.z + v1.z + v2.z + v3.z;
        acc.w += v0.w + v1.w + v2.w + v3.w;
    }
    for (; j < pe; j++) {
        int s = __ldg(&g_csr[j]);
        float4 v = ((const float4*)(g_y + (size_t)s * 128))[lane];
        acc.x += v.x; acc.y += v.y; acc.z += v.z; acc.w += v.w;
    }
    ((float4*)(g_agg + (size_t)n * 128))[lane] = acc;
}

// ------------------------------------------------------------------
// Fused MLP, 32 rows/block, 256 threads (8 warps, 2m x 4n). Unchanged from R13.
__global__ void __launch_bounds__(256) mlp_kernel(
    const float* __restrict__ feat, const int* __restrict__ labels,
    const float* __restrict__ g1, const float* __restrict__ be1,
    const float* __restrict__ b2)
{
    extern __shared__ float sm[];
    float* sH = sm;               // 16640 floats
    float* sA = sm + 32 * HS;     // 4352 floats

    const int tid = threadIdx.x;
    const int w   = tid >> 5;
    const int cl  = tid & 31;
    const int wm  = w & 1;
    const int wn  = w >> 1;
    const int n0g = blockIdx.x * 32;
    const int row0 = wm * 16;

    #pragma unroll
    for (int q = 0; q < 4; q++) {
        int i = tid + q * 256;
        int r = i >> 5, c4 = i & 31;
        float4 v = ((const float4*)feat)[(size_t)(n0g + r) * 32 + c4];
        v.x = tf32r(v.x); v.y = tf32r(v.y); v.z = tf32r(v.z); v.w = tf32r(v.w);
        ((float4*)(sA + r * AS))[c4] = v;
    }
    {
        const float4* src = (const float4*)g_w1r;
        #pragma unroll
        for (int q = 0; q < 4; q++) {
            int i = tid + q * 256;
            int r = i >> 7, c4 = i & 127;
            ((float4*)(sH + r * HS))[c4] = src[i];
        }
    }
    __syncthreads();

    wmma::fragment<wmma::accumulator, 16, 16, 8, float> c1[8];
    #pragma unroll
    for (int j = 0; j < 8; j++) wmma::fill_fragment(c1[j], 0.0f);

    const int n0 = wn * 128;
    for (int kt = 0; kt < 16; kt++) {
        const float* cur = sH + (kt & 1) * (8 * HS);

        wmma::fragment<wmma::matrix_a, 16, 16, 8, wmma::precision::tf32, wmma::row_major> a;
        wmma::load_matrix_sync(a, sA + row0 * AS + kt * 8, AS);

        #pragma unroll
        for (int j = 0; j < 8; j++) {
            wmma::fragment<wmma::matrix_b, 16, 16, 8, wmma::precision::tf32, wmma::row_major> b;
            wmma::load_matrix_sync(b, cur + n0 + j * 16, HS);
            wmma::mma_sync(c1[j], a, b, c1[j]);
        }

        if (kt < 15) {
            float* nxt = sH + ((kt + 1) & 1) * (8 * HS);
            const float4* src = (const float4*)g_w1r + (kt + 1) * 1024;
            #pragma unroll
            for (int q = 0; q < 4; q++) {
                int i = tid + q * 256;
                int r = i >> 7, c4 = i & 127;
                ((float4*)(nxt + r * HS))[c4] = src[i];
            }
        }
        __syncthreads();
    }

    #pragma unroll
    for (int j = 0; j < 8; j++)
        wmma::store_matrix_sync(sH + row0 * HS + n0 + j * 16, c1[j], HS, wmma::mem_row_major);
    __syncthreads();

    #pragma unroll
    for (int i = 0; i < 4; i++) {
        int r = w * 4 + i;
        const float* Ep = g_E + __ldg(&labels[n0g + r]) * 512;
        float vals[16];
        float s = 0.f;
        #pragma unroll
        for (int jj = 0; jj < 16; jj++) {
            int col = cl + 32 * jj;
            vals[jj] = sH[r * HS + col] + __ldg(&Ep[col]);
            s += vals[jj];
        }
        float mu = warp_sum(s) * (1.0f / 512.0f);
        float v = 0.f;
        #pragma unroll
        for (int jj = 0; jj < 16; jj++) {
            float d = vals[jj] - mu;
            v += d * d;
        }
        float rstd = rsqrtf(warp_sum(v) * (1.0f / 512.0f) + 1e-5f);
        #pragma unroll
        for (int jj = 0; jj < 16; jj++) {
            int col = cl + 32 * jj;
            float x = (vals[jj] - mu) * rstd * __ldg(&g1[col]) + __ldg(&be1[col]);
            sH[r * HS + col] = tf32r(fmaxf(x, 0.f));
        }
    }

    wmma::fragment<wmma::accumulator, 16, 16, 8, float> c2[2];
    wmma::fill_fragment(c2[0], 0.0f);
    wmma::fill_fragment(c2[1], 0.0f);

    const int n02 = wn * 32;
    for (int kt = 0; kt < 32; kt++) {
        __syncthreads();
        const float4* src = (const float4*)g_w2r + kt * 512;
        #pragma unroll
        for (int q = 0; q < 2; q++) {
            int i = tid + q * 256;
            int r = i >> 5, c4 = i & 31;
            ((float4*)(sA + r * AS))[c4] = src[i];
        }
        __syncthreads();

        #pragma unroll
        for (int ks = 0; ks < 2; ks++) {
            wmma::fragment<wmma::matrix_a, 16, 16, 8, wmma::precision::tf32, wmma::row_major> a2;
            wmma::load_matrix_sync(a2, sH + row0 * HS + kt * 16 + ks * 8, HS);
            #pragma unroll
            for (int j = 0; j < 2; j++) {
                wmma::fragment<wmma::matrix_b, 16, 16, 8, wmma::precision::tf32, wmma::row_major> b;
                wmma::load_matrix_sync(b, sA + (ks * 8) * AS + n02 + j * 16, AS);
                wmma::mma_sync(c2[j], a2, b, c2[j]);
            }
        }
    }
    __syncthreads();

    #pragma unroll
    for (int j = 0; j < 2; j++)
        wmma::store_matrix_sync(sA + row0 * 128 + n02 + j * 16, c2[j], 128, wmma::mem_row_major);
    __syncthreads();

    for (int i = tid; i < 4096; i += 256) {
        int r = i >> 7, col = i & 127;
        int row = n0g + r;
        g_y[(size_t)row * 128 + col] = (sA[i] + __ldg(&b2[col])) * g_ns[row];
    }
}

// ------------------------------------------------------------------
// Conv transform on tf32 wmma (unchanged).
__global__ void __launch_bounds__(256) conv_kernel(
    const float* __restrict__ bc, float* __restrict__ out_ext,
    int which, int to_y)
{
    __shared__ float sA[32 * AS];
    __shared__ float sW[2][16 * AS];

    const float* Wcr = which ? g_wc1r : g_wc0r;
    const int tid = threadIdx.x;
    const int w   = tid >> 5;
    const int wm  = w & 1;
    const int wn  = w >> 1;
    const int n0  = blockIdx.x * 32;

    #pragma unroll
    for (int q = 0; q < 4; q++) {
        int i = tid + q * 256;
        int r = i >> 5, c4 = i & 31;
        float4 v = ((const float4*)g_agg)[(size_t)(n0 + r) * 32 + c4];
        float ndv = g_nd[n0 + r];
        v.x = tf32r(v.x * ndv); v.y = tf32r(v.y * ndv);
        v.z = tf32r(v.z * ndv); v.w = tf32r(v.w * ndv);
        ((float4*)(sA + r * AS))[c4] = v;
    }
    {
        const float4* src = (const float4*)Wcr;
        #pragma unroll
        for (int q = 0; q < 2; q++) {
            int i = tid + q * 256;
            int r = i >> 5, c4 = i & 31;
            ((float4*)(sW[0] + r * AS))[c4] = src[i];
        }
    }
    __syncthreads();

    wmma::fragment<wmma::accumulator, 16, 16, 8, float> c[2];
    wmma::fill_fragment(c[0], 0.0f);
    wmma::fill_fragment(c[1], 0.0f);

    for (int kt = 0; kt < 8; kt++) {
        float4 pre[2];
        if (kt < 7) {
            const float4* src = (const float4*)Wcr + (kt + 1) * 512;
            #pragma unroll
            for (int q = 0; q < 2; q++) pre[q] = src[tid + q * 256];
        }
        const float* cur = sW[kt & 1];

        #pragma unroll
        for (int ks = 0; ks < 2; ks++) {
            wmma::fragment<wmma::matrix_a, 16, 16, 8, wmma::precision::tf32, wmma::row_major> a;
            wmma::load_matrix_sync(a, sA + (wm * 16) * AS + kt * 16 + ks * 8, AS);
            #pragma unroll
            for (int j = 0; j < 2; j++) {
                wmma::fragment<wmma::matrix_b, 16, 16, 8, wmma::precision::tf32, wmma::row_major> b;
                wmma::load_matrix_sync(b, cur + (ks * 8) * AS + wn * 32 + j * 16, AS);
                wmma::mma_sync(c[j], a, b, c[j]);
            }
        }

        if (kt < 7) {
            float* nxt = sW[(kt + 1) & 1];
            #pragma unroll
            for (int q = 0; q < 2; q++) {
                int i = tid + q * 256;
                int r = i >> 5, c4 = i & 31;
                ((float4*)(nxt + r * AS))[c4] = pre[q];
            }
        }
        __syncthreads();
    }

    #pragma unroll
    for (int j = 0; j < 2; j++)
        wmma::store_matrix_sync(sA + (wm * 16) * 128 + wn * 32 + j * 16,
                                c[j], 128, wmma::mem_row_major);
    __syncthreads();

    for (int i = tid; i < 4096; i += 256) {
        int r = i >> 7, col = i & 127;
        int row = n0 + r;
        float z = fmaxf(sA[i] + __ldg(&bc[col]), 0.f);
        if (to_y) g_y[(size_t)row * 128 + col] = z * g_ns[row];
        else      out_ext[(size_t)row * 128 + col] = z;
    }
}

// ------------------------------------------------------------------
extern "C" void kernel_launch(void* const* d_in, const int* in_sizes, int n_in,
                              void* d_out, int out_size)
{
    const float* feat   = (const float*)d_in[0];
    const int*   labels = (const int*)  d_in[1];
    const int*   esrc   = (const int*)  d_in[2];
    const int*   edst   = (const int*)  d_in[3];
    const float* emb    = (const float*)d_in[4];
    const float* W1     = (const float*)d_in[5];
    const float* b1     = (const float*)d_in[6];
    const float* g1     = (const float*)d_in[7];
    const float* be1    = (const float*)d_in[8];
    const float* W2     = (const float*)d_in[9];
    const float* b2     = (const float*)d_in[10];
    const float* Wc0    = (const float*)d_in[11];
    const float* bc0    = (const float*)d_in[12];
    const float* Wc1    = (const float*)d_in[13];
    const float* bc1    = (const float*)d_in[14];
    float* out = (float*)d_out;

    cudaFuncSetAttribute(mlp_kernel, cudaFuncAttributeMaxDynamicSharedMemorySize,
                         MLP_SMEM_BYTES);

    // launch order puts mlp 4th (ncu capture window)
    zero_deg_kernel<<<(NN + 255) / 256, 256>>>();
    deg_round_kernel<<<(EE + 255) / 256, 256>>>(esrc, edst, W1, W2, Wc0, Wc1);
    norm_prep_kernel<<<(NN + 255) / 256, 256>>>(emb, W1, b1);
    mlp_kernel<<<NN / 32, 256, MLP_SMEM_BYTES>>>(feat, labels, g1, be1, b2);

    fill_kernel<<<(EE + 255) / 256, 256>>>(esrc, edst);

    // layer 1
    gather_kernel<<<(NN * 32 + 255) / 256, 256>>>();
    conv_kernel<<<NN / 32, 256>>>(bc0, nullptr, 0, 1);

    // layer 2
    gather_kernel<<<(NN * 32 + 255) / 256, 256>>>();
    conv_kernel<<<NN / 32, 256>>>(bc1, out, 1, 0);
}